// round 15
// baseline (speedup 1.0000x reference)
#include <cuda_runtime.h>
#include <cstdint>

#define N_TOK 4096
#define D_MODEL 512
#define K_LR 256
#define H_HEADS 8
#define DHEAD 64
#define D_FF 2048
#define EPS_LN 1e-5f
#define ATTN_SCALE 0.125f
#define NSPLIT 32
#define KT 16

#define ND ((long long)N_TOK * D_MODEL)
#define KD ((long long)K_LR * D_MODEL)
#define NK ((long long)N_TOK * K_LR)
#define HNK ((long long)H_HEADS * NK)
#define NFF ((long long)N_TOK * D_FF)

#define NDH 1048576LL
#define KDH 65536LL
#define NKH 524288LL
#define HNKH 4194304LL
#define NFFH 4194304LL

// ---------------- scratch ----------------
__device__ unsigned g_Nsp[4 * NDH];
__device__ unsigned g_Qsp[4 * NDH];
__device__ float    g_KVf[4 * ND];
__device__ unsigned g_KPsp[6 * KDH];
__device__ unsigned g_VPsp[6 * KDH];
__device__ unsigned g_Dsp[4 * HNKH];
__device__ unsigned g_Osp[4 * NDH];
__device__ unsigned g_Hsp[4 * NFFH];
__device__ float    g_PSUM[4 * NSPLIT * KD];
__device__ unsigned g_Wq[2 * 262144];
__device__ unsigned g_Wk[2 * 262144];
__device__ unsigned g_Wv[2 * 262144];
__device__ unsigned g_Wo[2 * 262144];
__device__ unsigned g_W1r[2 * 1048576];
__device__ unsigned g_W1i[4 * 1048576];
__device__ unsigned g_W2r[2 * 1048576];
__device__ unsigned g_W2i[4 * 1048576];

// ---------------- helpers ----------------
__device__ __forceinline__ unsigned packbf(float x0, float x1) {
    unsigned r;
    asm("cvt.rn.bf16x2.f32 %0, %1, %2;" : "=r"(r) : "f"(x1), "f"(x0));
    return r;
}
__device__ __forceinline__ void split2(float x0, float x1, unsigned& hi, unsigned& lo) {
    hi = packbf(x0, x1);
    float h0 = __uint_as_float(hi << 16);
    float h1 = __uint_as_float(hi & 0xffff0000u);
    lo = packbf(x0 - h0, x1 - h1);
}
__device__ __forceinline__ void mma_bf16(float* c, const unsigned* a, const unsigned* b) {
    asm volatile(
        "mma.sync.aligned.m16n8k16.row.col.f32.bf16.bf16.f32 "
        "{%0,%1,%2,%3}, {%4,%5,%6,%7}, {%8,%9}, {%0,%1,%2,%3};\n"
        : "+f"(c[0]), "+f"(c[1]), "+f"(c[2]), "+f"(c[3])
        : "r"(a[0]), "r"(a[1]), "r"(a[2]), "r"(a[3]), "r"(b[0]), "r"(b[1]));
}
__device__ __forceinline__ void ldm4(unsigned* r, unsigned addr) {
    asm volatile(
        "ldmatrix.sync.aligned.m8n8.x4.shared.b16 {%0,%1,%2,%3}, [%4];"
        : "=r"(r[0]), "=r"(r[1]), "=r"(r[2]), "=r"(r[3])
        : "r"(addr));
}
__device__ __forceinline__ void cpasync16(unsigned dst, const void* src, int srcsize) {
    asm volatile("cp.async.cg.shared.global [%0], [%1], 16, %2;"
                 :: "r"(dst), "l"(src), "r"(srcsize) : "memory");
}
#define CP_COMMIT() asm volatile("cp.async.commit_group;" ::: "memory")
#define CP_WAIT1() asm volatile("cp.async.wait_group 1;" ::: "memory")

// ---------------- block reduction ----------------
__device__ __forceinline__ float blockSum(float v, float* red) {
#pragma unroll
    for (int o = 16; o > 0; o >>= 1) v += __shfl_xor_sync(0xffffffffu, v, o);
    int lane = threadIdx.x & 31, w = threadIdx.x >> 5;
    if (lane == 0) red[w] = v;
    __syncthreads();
    if (w == 0) {
        float x = (lane < 16) ? red[lane] : 0.f;
#pragma unroll
        for (int o = 8; o > 0; o >>= 1) x += __shfl_xor_sync(0xffffffffu, x, o);
        if (lane == 0) red[0] = x;
    }
    __syncthreads();
    float r = red[0];
    __syncthreads();
    return r;
}

// ---------------- complex layernorm -> split bf16 ----------------
__global__ void cln_kernel(const float* __restrict__ xr, const float* __restrict__ xi,
                           unsigned* __restrict__ Nsp) {
    __shared__ float red[16];
    int row = blockIdx.x;
    int t = threadIdx.x;
    long long base = (long long)row * D_MODEL;
    float vr = xr[base + t];
    float vi = xi[base + t];
    const float invD = 1.0f / D_MODEL;
    float mr = blockSum(vr, red) * invD;
    float mi = blockSum(vi, red) * invD;
    float cr = vr - mr, ci = vi - mi;
    float Crr = blockSum(cr * cr, red) * invD + EPS_LN;
    float Cii = blockSum(ci * ci, red) * invD + EPS_LN;
    float Cri = blockSum(cr * ci, red) * invD;
    float s = sqrtf(Crr * Cii - Cri * Cri);
    float tt = sqrtf(Cii + Crr + 2.0f * s);
    float inv = 1.0f / (s * tt);
    float Rrr = (Cii + s) * inv;
    float Rii = (Crr + s) * inv;
    float Rri = -Cri * inv;
    float outr = Rrr * cr + Rri * ci;
    float outi = Rii * ci + Rri * cr;
    float outr2 = __shfl_down_sync(0xffffffffu, outr, 1);
    float outi2 = __shfl_down_sync(0xffffffffu, outi, 1);
    if ((t & 1) == 0) {
        long long o = (long long)row * (D_MODEL / 2) + (t >> 1);
        unsigned h, l;
        split2(outr, outr2, h, l);
        Nsp[o] = h;
        Nsp[NDH + o] = l;
        split2(outi, outi2, h, l);
        Nsp[2 * NDH + o] = h;
        Nsp[3 * NDH + o] = l;
    }
}

// ---------------- cp.async 3-stage TB GEMM (R8 mainloop; HN = 64-col tiles) --
template <bool HN>
__global__ void __launch_bounds__(256, 2) gemm_sp(
    const unsigned* __restrict__ A1h, const unsigned* __restrict__ A1l,
    const unsigned* __restrict__ A2h, const unsigned* __restrict__ A2l,
    const unsigned* __restrict__ B1h, const unsigned* __restrict__ B1l,
    const unsigned* __restrict__ B2h, const unsigned* __restrict__ B2l,
    const unsigned* __restrict__ B2nh, const unsigned* __restrict__ B2nl,
    float* __restrict__ Cf, unsigned* __restrict__ Ch, unsigned* __restrict__ Cl,
    const float* __restrict__ bias1, const float* __restrict__ bias2,
    int M, int N, int Kd, int ldap, int ldbp, int ldc,
    long long sAp, long long sBp, long long sC, long long sCp,
    float alpha, float beta, int nzc, int dorelu) {
    __shared__ unsigned smem[3 * 4096];

    const int z = blockIdx.z;
    const int part = (nzc == 2) ? (z & 1) : 0;
    const int bz = (nzc == 2) ? (z >> 1) : z;

    const unsigned* Ac0h = A1h + bz * sAp;
    const unsigned* Ac0l = A1l + bz * sAp;
    const unsigned* Ac1h = A2h ? A2h + bz * sAp : nullptr;
    const unsigned* Ac1l = A2h ? A2l + bz * sAp : nullptr;
    const unsigned *Bc0h, *Bc0l, *Bc1h = nullptr, *Bc1l = nullptr;
    const float* biasz;
    if (part == 0) {
        Bc0h = B1h + bz * sBp;
        Bc0l = B1l + bz * sBp;
        if (A2h) {
            Bc1h = B2nh + bz * sBp;
            Bc1l = B2nl + bz * sBp;
        }
        biasz = bias1;
    } else {
        Bc0h = B2h + bz * sBp;
        Bc0l = B2l + bz * sBp;
        Bc1h = B1h + bz * sBp;
        Bc1l = B1l + bz * sBp;
        biasz = bias2;
    }
    float* Cfb = Cf ? Cf + bz * sC + (long long)part * sCp : nullptr;
    unsigned* Chb = Ch ? Ch + bz * sC + (long long)part * sCp : nullptr;
    unsigned* Clb = Ch ? Cl + bz * sC + (long long)part * sCp : nullptr;

    const int TILE_N = HN ? 64 : 128;
    const int brow = blockIdx.y * 128, bcol = blockIdx.x * TILE_N;
    const int tid = threadIdx.x;
    const int lane = tid & 31, w = tid >> 5;
    const int wr = HN ? (w >> 1) : (w >> 2);
    const int wc = HN ? (w & 1) : (w & 3);
    const int WROW = HN ? 32 : 64;
    const int MT = HN ? 2 : 4;
    const int gr = lane >> 2, gc = lane & 3;

    float acc[4][4][4];
#pragma unroll
    for (int i = 0; i < 4; i++)
#pragma unroll
        for (int j = 0; j < 4; j++)
#pragma unroll
            for (int q = 0; q < 4; q++) acc[i][j][q] = 0.f;

    const int am = tid >> 1, kh = tid & 1;
    const unsigned a_idx = am * 8 + ((kh ^ ((am >> 2) & 1)) * 4);

    const int lm_row = ((lane >> 3) & 1) * 8 + (lane & 7);
    const int lm_g = lane >> 4;
    const int a_mb = wr * WROW + lm_row;
    const unsigned a_frag = (a_mb * 8 + ((lm_g ^ ((a_mb >> 2) & 1)) * 4)) * 4;
    const int b_nb = wc * 32 + lm_row;
    const unsigned b_frag = (b_nb * 8 + ((lm_g ^ ((b_nb >> 2) & 1)) * 4)) * 4;

    const unsigned sbase = (unsigned)__cvta_generic_to_shared(&smem[0]);

    const int ntile1 = Kd / KT;
    const int ntot = (A2h ? 2 : 1) * ntile1;
    const int gn = bcol + am;
    const int bok = (gn < N && am < TILE_N) ? 16 : 0;
    const int gnc = bok ? gn : 0;

    auto ldst = [&](int t, int stage) {
        int ch = (t >= ntile1);
        const unsigned* Ah = ch ? Ac1h : Ac0h;
        const unsigned* Al = ch ? Ac1l : Ac0l;
        const unsigned* Bh = ch ? Bc1h : Bc0h;
        const unsigned* Bl = ch ? Bc1l : Bc0l;
        int k0p = (ch ? t - ntile1 : t) * 8;
        unsigned sa = sbase + stage * 16384 + a_idx * 4;
        long long aoff = (long long)(brow + am) * ldap + k0p + kh * 4;
        cpasync16(sa, Ah + aoff, 16);
        cpasync16(sa + 4096, Al + aoff, 16);
        long long boff = (long long)gnc * ldbp + k0p + kh * 4;
        cpasync16(sa + 8192, Bh + boff, bok);
        cpasync16(sa + 12288, Bl + boff, bok);
    };
    auto compute = [&](int stage) {
        unsigned bufA = sbase + stage * 16384;
        unsigned bufB = bufA + 8192;
        unsigned bh[4][2], bl[4][2];
#pragma unroll
        for (int p = 0; p < 2; p++) {
            unsigned r[4];
            ldm4(r, bufB + b_frag + p * 512);
            bh[2 * p][0] = r[0]; bh[2 * p + 1][0] = r[1];
            bh[2 * p][1] = r[2]; bh[2 * p + 1][1] = r[3];
            ldm4(r, bufB + 4096 + b_frag + p * 512);
            bl[2 * p][0] = r[0]; bl[2 * p + 1][0] = r[1];
            bl[2 * p][1] = r[2]; bl[2 * p + 1][1] = r[3];
        }
#pragma unroll
        for (int mt = 0; mt < MT; mt++) {
            unsigned ah[4], al[4];
            ldm4(ah, bufA + a_frag + mt * 512);
            ldm4(al, bufA + 4096 + a_frag + mt * 512);
#pragma unroll
            for (int nt = 0; nt < 4; nt++) {
                mma_bf16(acc[mt][nt], ah, bh[nt]);
                mma_bf16(acc[mt][nt], al, bh[nt]);
                mma_bf16(acc[mt][nt], ah, bl[nt]);
            }
        }
    };

    ldst(0, 0);
    CP_COMMIT();
    if (ntot > 1) ldst(1, 1);
    CP_COMMIT();
    for (int t = 0; t < ntot; t++) {
        CP_WAIT1();
        __syncthreads();
        if (t + 2 < ntot) ldst(t + 2, (t + 2) % 3);
        CP_COMMIT();
        compute(t % 3);
    }

    const int ldcP = ldc >> 1;
#pragma unroll
    for (int mt = 0; mt < MT; mt++) {
        int m0 = brow + wr * WROW + mt * 16 + gr;
#pragma unroll
        for (int nt = 0; nt < 4; nt++) {
            int n0 = bcol + wc * 32 + nt * 8 + gc * 2;
            if (n0 >= N) continue;
            const float* c = acc[mt][nt];
            float b0 = 0.f, b1v = 0.f;
            if (biasz) {
                b0 = biasz[n0];
                b1v = biasz[n0 + 1];
            }
            float v0 = alpha * c[0] + b0, v1 = alpha * c[1] + b1v;
            float v2 = alpha * c[2] + b0, v3 = alpha * c[3] + b1v;
            if (dorelu) {
                v0 = fmaxf(v0, 0.f); v1 = fmaxf(v1, 0.f);
                v2 = fmaxf(v2, 0.f); v3 = fmaxf(v3, 0.f);
            }
            if (Cfb) {
                long long off = (long long)m0 * ldc + n0;
                float2 o;
                if (beta != 0.f) {
                    o = *(const float2*)&Cfb[off];
                    v0 += beta * o.x; v1 += beta * o.y;
                }
                *(float2*)&Cfb[off] = make_float2(v0, v1);
                off += (long long)8 * ldc;
                if (beta != 0.f) {
                    o = *(const float2*)&Cfb[off];
                    v2 += beta * o.x; v3 += beta * o.y;
                }
                *(float2*)&Cfb[off] = make_float2(v2, v3);
            }
            if (Chb) {
                unsigned h, l;
                long long off = (long long)m0 * ldcP + (n0 >> 1);
                split2(v0, v1, h, l);
                Chb[off] = h; Clb[off] = l;
                off += (long long)8 * ldcP;
                split2(v2, v3, h, l);
                Chb[off] = h; Clb[off] = l;
            }
        }
    }
}

// ---------------- fused QKV GEMM: z = wsel(3) x part(2) ----------------------
__global__ void __launch_bounds__(256, 2) gemm_qkv(
    const unsigned* __restrict__ Nsp,
    const unsigned* __restrict__ Bqh, const unsigned* __restrict__ Bql,
    const unsigned* __restrict__ Bkh, const unsigned* __restrict__ Bkl,
    const unsigned* __restrict__ Bvh, const unsigned* __restrict__ Bvl,
    unsigned* __restrict__ Qsp, float* __restrict__ KVf,
    const float* __restrict__ bq, const float* __restrict__ bk,
    const float* __restrict__ bv) {
    __shared__ unsigned smem[3 * 4096];

    const int z = blockIdx.z;
    const int part = z & 1, wsel = z >> 1;
    const unsigned* Azh = Nsp + (long long)part * 2 * NDH;
    const unsigned* Azl = Azh + NDH;
    const unsigned* Bzh = (wsel == 0) ? Bqh : (wsel == 1) ? Bkh : Bvh;
    const unsigned* Bzl = (wsel == 0) ? Bql : (wsel == 1) ? Bkl : Bvl;
    const float* biasz = (wsel == 0) ? bq : (wsel == 1) ? bk : bv;
    unsigned* Chb = (wsel == 0) ? Qsp + (long long)part * 2 * NDH : nullptr;
    unsigned* Clb = Chb ? Chb + NDH : nullptr;
    float* Cfb = (wsel == 0) ? nullptr : KVf + (long long)(wsel - 1) * 2 * ND + (long long)part * ND;

    const int brow = blockIdx.y * 128, bcol = blockIdx.x * 128;
    const int tid = threadIdx.x;
    const int lane = tid & 31, w = tid >> 5;
    const int wr = w >> 2, wc = w & 3;
    const int gr = lane >> 2, gc = lane & 3;

    float acc[4][4][4];
#pragma unroll
    for (int i = 0; i < 4; i++)
#pragma unroll
        for (int j = 0; j < 4; j++)
#pragma unroll
            for (int q = 0; q < 4; q++) acc[i][j][q] = 0.f;

    const int am = tid >> 1, kh = tid & 1;
    const unsigned a_idx = am * 8 + ((kh ^ ((am >> 2) & 1)) * 4);
    const int lm_row = ((lane >> 3) & 1) * 8 + (lane & 7);
    const int lm_g = lane >> 4;
    const int a_mb = wr * 64 + lm_row;
    const unsigned a_frag = (a_mb * 8 + ((lm_g ^ ((a_mb >> 2) & 1)) * 4)) * 4;
    const int b_nb = wc * 32 + lm_row;
    const unsigned b_frag = (b_nb * 8 + ((lm_g ^ ((b_nb >> 2) & 1)) * 4)) * 4;
    const unsigned sbase = (unsigned)__cvta_generic_to_shared(&smem[0]);

    const int ntot = D_MODEL / KT;  // 32
    const int gn = bcol + am;

    auto ldst = [&](int t, int stage) {
        int k0p = t * 8;
        unsigned sa = sbase + stage * 16384 + a_idx * 4;
        long long aoff = (long long)(brow + am) * 256 + k0p + kh * 4;
        cpasync16(sa, Azh + aoff, 16);
        cpasync16(sa + 4096, Azl + aoff, 16);
        long long boff = (long long)gn * 256 + k0p + kh * 4;
        cpasync16(sa + 8192, Bzh + boff, 16);
        cpasync16(sa + 12288, Bzl + boff, 16);
    };
    auto compute = [&](int stage) {
        unsigned bufA = sbase + stage * 16384;
        unsigned bufB = bufA + 8192;
        unsigned bh[4][2], bl[4][2];
#pragma unroll
        for (int p = 0; p < 2; p++) {
            unsigned r[4];
            ldm4(r, bufB + b_frag + p * 512);
            bh[2 * p][0] = r[0]; bh[2 * p + 1][0] = r[1];
            bh[2 * p][1] = r[2]; bh[2 * p + 1][1] = r[3];
            ldm4(r, bufB + 4096 + b_frag + p * 512);
            bl[2 * p][0] = r[0]; bl[2 * p + 1][0] = r[1];
            bl[2 * p][1] = r[2]; bl[2 * p + 1][1] = r[3];
        }
#pragma unroll
        for (int mt = 0; mt < 4; mt++) {
            unsigned ah[4], al[4];
            ldm4(ah, bufA + a_frag + mt * 512);
            ldm4(al, bufA + 4096 + a_frag + mt * 512);
#pragma unroll
            for (int nt = 0; nt < 4; nt++) {
                mma_bf16(acc[mt][nt], ah, bh[nt]);
                mma_bf16(acc[mt][nt], al, bh[nt]);
                mma_bf16(acc[mt][nt], ah, bl[nt]);
            }
        }
    };

    ldst(0, 0);
    CP_COMMIT();
    ldst(1, 1);
    CP_COMMIT();
    for (int t = 0; t < ntot; t++) {
        CP_WAIT1();
        __syncthreads();
        if (t + 2 < ntot) ldst(t + 2, (t + 2) % 3);
        CP_COMMIT();
        compute(t % 3);
    }

#pragma unroll
    for (int mt = 0; mt < 4; mt++) {
        int m0 = brow + wr * 64 + mt * 16 + gr;
#pragma unroll
        for (int nt = 0; nt < 4; nt++) {
            int n0 = bcol + wc * 32 + nt * 8 + gc * 2;
            const float* c = acc[mt][nt];
            float b0 = biasz[n0], b1v = biasz[n0 + 1];
            float v0 = c[0] + b0, v1 = c[1] + b1v;
            float v2 = c[2] + b0, v3 = c[3] + b1v;
            if (Cfb) {
                long long off = (long long)m0 * 512 + n0;
                *(float2*)&Cfb[off] = make_float2(v0, v1);
                *(float2*)&Cfb[off + 8 * 512] = make_float2(v2, v3);
            } else {
                unsigned h, l;
                long long off = (long long)m0 * 256 + (n0 >> 1);
                split2(v0, v1, h, l);
                Chb[off] = h; Clb[off] = l;
                off += 8 * 256;
                split2(v2, v3, h, l);
                Chb[off] = h; Clb[off] = l;
            }
        }
    }
}

// ---------------- split-K projection (unchanged) ----------
__global__ void __launch_bounds__(256, 2) proj_splitk_tc(
    const float* __restrict__ pk, const float* __restrict__ pv,
    const float* __restrict__ KV, float* __restrict__ P) {
    __shared__ unsigned As[2][2][8 * 136];
    __shared__ unsigned Bs[2][2][8 * 136];
    const int z = blockIdx.z;
    const int p = z >> 5;
    const int s = z & 31;
    const float* A = (p < 2) ? pk : pv;
    const float* B = KV + (long long)p * ND;
    const int chunk = N_TOK / NSPLIT;
    const int kbeg = s * chunk;
    const int brow = blockIdx.y * 128, bcol = blockIdx.x * 128;
    const int tid = threadIdx.x;
    const int lane = tid & 31, w = tid >> 5;
    const int wr = w >> 2, wc = w & 3;
    const int gr = lane >> 2, gc = lane & 3;
    const int kp = tid >> 5;
    const int an = lane * 4;

    float acc[4][4][4];
#pragma unroll
    for (int i = 0; i < 4; i++)
#pragma unroll
        for (int j = 0; j < 4; j++)
#pragma unroll
            for (int q = 0; q < 4; q++) acc[i][j][q] = 0.f;

    float4 pa0, pa1, pb0, pb1;
    auto ld = [&](int k0) {
        pa0 = *(const float4*)&A[(long long)(k0 + 2 * kp) * K_LR + brow + an];
        pa1 = *(const float4*)&A[(long long)(k0 + 2 * kp + 1) * K_LR + brow + an];
        pb0 = *(const float4*)&B[(long long)(k0 + 2 * kp) * D_MODEL + bcol + an];
        pb1 = *(const float4*)&B[(long long)(k0 + 2 * kp + 1) * D_MODEL + bcol + an];
    };
    auto st = [&](int buf) {
        unsigned h, l;
        unsigned base = kp * 136 + an;
        split2(pa0.x, pa1.x, h, l); As[buf][0][base + 0] = h; As[buf][1][base + 0] = l;
        split2(pa0.y, pa1.y, h, l); As[buf][0][base + 1] = h; As[buf][1][base + 1] = l;
        split2(pa0.z, pa1.z, h, l); As[buf][0][base + 2] = h; As[buf][1][base + 2] = l;
        split2(pa0.w, pa1.w, h, l); As[buf][0][base + 3] = h; As[buf][1][base + 3] = l;
        split2(pb0.x, pb1.x, h, l); Bs[buf][0][base + 0] = h; Bs[buf][1][base + 0] = l;
        split2(pb0.y, pb1.y, h, l); Bs[buf][0][base + 1] = h; Bs[buf][1][base + 1] = l;
        split2(pb0.z, pb1.z, h, l); Bs[buf][0][base + 2] = h; Bs[buf][1][base + 2] = l;
        split2(pb0.w, pb1.w, h, l); Bs[buf][0][base + 3] = h; Bs[buf][1][base + 3] = l;
    };
    auto compute = [&](int buf) {
        unsigned bh[4][2], bl[4][2];
#pragma unroll
        for (int nt = 0; nt < 4; nt++) {
            int n = wc * 32 + nt * 8 + gr;
            bh[nt][0] = Bs[buf][0][gc * 136 + n];
            bh[nt][1] = Bs[buf][0][(gc + 4) * 136 + n];
            bl[nt][0] = Bs[buf][1][gc * 136 + n];
            bl[nt][1] = Bs[buf][1][(gc + 4) * 136 + n];
        }
#pragma unroll
        for (int mt = 0; mt < 4; mt++) {
            int m = wr * 64 + mt * 16;
            unsigned ah[4], al[4];
            ah[0] = As[buf][0][gc * 136 + m + gr];
            ah[1] = As[buf][0][gc * 136 + m + 8 + gr];
            ah[2] = As[buf][0][(gc + 4) * 136 + m + gr];
            ah[3] = As[buf][0][(gc + 4) * 136 + m + 8 + gr];
            al[0] = As[buf][1][gc * 136 + m + gr];
            al[1] = As[buf][1][gc * 136 + m + 8 + gr];
            al[2] = As[buf][1][(gc + 4) * 136 + m + gr];
            al[3] = As[buf][1][(gc + 4) * 136 + m + 8 + gr];
#pragma unroll
            for (int nt = 0; nt < 4; nt++) {
                mma_bf16(acc[mt][nt], ah, bh[nt]);
                mma_bf16(acc[mt][nt], al, bh[nt]);
                mma_bf16(acc[mt][nt], ah, bl[nt]);
            }
        }
    };

    ld(kbeg);
    st(0);
    __syncthreads();
    const int ntile = chunk / KT;
    for (int t = 0; t < ntile; t++) {
        if (t + 1 < ntile) ld(kbeg + (t + 1) * KT);
        compute(t & 1);
        if (t + 1 < ntile) st((t + 1) & 1);
        __syncthreads();
    }

    float* Pz = P + (long long)z * KD;
#pragma unroll
    for (int mt = 0; mt < 4; mt++) {
        int m0 = brow + wr * 64 + mt * 16 + gr;
#pragma unroll
        for (int nt = 0; nt < 4; nt++) {
            int n0 = bcol + wc * 32 + nt * 8 + gc * 2;
            const float* c = acc[mt][nt];
            *(float2*)&Pz[(long long)m0 * D_MODEL + n0] = make_float2(c[0], c[1]);
            *(float2*)&Pz[(long long)(m0 + 8) * D_MODEL + n0] = make_float2(c[2], c[3]);
        }
    }
}

// reduce split-K partials; KP: [K_LR][D/2] pairs along D; VP: TB [D][K_LR/2]
__global__ void proj_reduce_sp(const float* __restrict__ P,
                               unsigned* __restrict__ KP, unsigned* __restrict__ VP) {
    const int half = (int)KDH;
    int i = blockIdx.x * blockDim.x + threadIdx.x;
    if (i >= 4 * half) return;
    int p = i / half, j = i % half;
    long long e0, e1;
    if (p < 2) {
        int row = j / (D_MODEL / 2), c = j % (D_MODEL / 2);
        e0 = (long long)row * D_MODEL + 2 * c;
        e1 = e0 + 1;
    } else {
        int dm = j / (K_LR / 2), kp2 = j % (K_LR / 2);
        e0 = (long long)(2 * kp2) * D_MODEL + dm;
        e1 = e0 + D_MODEL;
    }
    const float* base = P + (long long)p * NSPLIT * KD;
    float s0 = 0.f, s1 = 0.f;
#pragma unroll 8
    for (int s = 0; s < NSPLIT; s++) {
        s0 += base[(long long)s * KD + e0];
        s1 += base[(long long)s * KD + e1];
    }
    unsigned h, l;
    split2(s0, s1, h, l);
    unsigned* T = (p < 2) ? KP : VP;
    int q = p & 1;
    T[(long long)(2 * q) * half + j] = h;
    T[(long long)(2 * q + 1) * half + j] = l;
    if (q == 1) {
        T[4LL * half + j] = h ^ 0x80008000u;
        T[5LL * half + j] = l ^ 0x80008000u;
    }
}

// fp32 W [DEPTH][Kd][N] -> TB split [depth][N][Kd/2] (+ optional negated)
__global__ void conv_TB(const float* __restrict__ W, unsigned* __restrict__ Wh,
                        unsigned* __restrict__ Wl, unsigned* __restrict__ Wnh,
                        unsigned* __restrict__ Wnl, int halfK, int N) {
    long long i = (long long)blockIdx.x * blockDim.x + threadIdx.x;
    long long per = (long long)halfK * N;
    if (i >= 2 * per) return;
    int d = (int)(i / per);
    long long r = i % per;
    int n = (int)(r / halfK);
    int kp = (int)(r % halfK);
    long long src = ((long long)d * 2 * halfK + 2 * kp) * N + n;
    unsigned h, l;
    split2(W[src], W[src + N], h, l);
    long long o = (long long)d * per + (long long)n * halfK + kp;
    Wh[o] = h;
    Wl[o] = l;
    if (Wnh) {
        Wnh[o] = h ^ 0x80008000u;
        Wnl[o] = l ^ 0x80008000u;
    }
}

// ---------------- host launcher ----------------
static inline void gemmSP(const unsigned* A1h, const unsigned* A1l,
                          const unsigned* A2h, const unsigned* A2l,
                          const unsigned* B1h, const unsigned* B1l,
                          const unsigned* B2h, const unsigned* B2l,
                          const unsigned* B2nh, const unsigned* B2nl,
                          float* Cf, unsigned* Ch, unsigned* Cl,
                          const float* b1, const float* b2,
                          int M, int N, int Kd, int ldap, int ldbp, int ldc,
                          long long sAp, long long sBp, long long sC, long long sCp,
                          int nbatch, int nzc, float alpha, float beta, int relu,
                          bool hn) {
    if (hn) {
        dim3 grid((N + 63) / 64, (M + 127) / 128, nbatch * nzc);
        gemm_sp<true><<<grid, 256>>>(A1h, A1l, A2h, A2l, B1h, B1l, B2h, B2l, B2nh, B2nl,
                                     Cf, Ch, Cl, b1, b2, M, N, Kd, ldap, ldbp, ldc,
                                     sAp, sBp, sC, sCp, alpha, beta, nzc, relu);
    } else {
        dim3 grid((N + 127) / 128, (M + 127) / 128, nbatch * nzc);
        gemm_sp<false><<<grid, 256>>>(A1h, A1l, A2h, A2l, B1h, B1l, B2h, B2l, B2nh, B2nl,
                                      Cf, Ch, Cl, b1, b2, M, N, Kd, ldap, ldbp, ldc,
                                      sAp, sBp, sC, sCp, alpha, beta, nzc, relu);
    }
}

extern "C" void kernel_launch(void* const* d_in, const int* in_sizes, int n_in,
                              void* d_out, int out_size) {
    const float* x_real = (const float*)d_in[0];
    const float* x_imag = (const float*)d_in[1];
    const float* Wq = (const float*)d_in[2];
    const float* bq = (const float*)d_in[3];
    const float* Wk = (const float*)d_in[4];
    const float* bk = (const float*)d_in[5];
    const float* Wv = (const float*)d_in[6];
    const float* bv = (const float*)d_in[7];
    const float* pk = (const float*)d_in[8];
    const float* pv = (const float*)d_in[9];
    const float* Wout = (const float*)d_in[10];
    const float* bout = (const float*)d_in[11];
    const float* W1r = (const float*)d_in[12];
    const float* W1i = (const float*)d_in[13];
    const float* b1r = (const float*)d_in[14];
    const float* b1i = (const float*)d_in[15];
    const float* W2r = (const float*)d_in[16];
    const float* W2i = (const float*)d_in[17];
    const float* b2r = (const float*)d_in[18];
    const float* b2i = (const float*)d_in[19];

    float* xr = (float*)d_out;
    float* xi = xr + ND;

    unsigned *Nsp, *Qsp, *KPsp, *VPsp, *Dsp, *Osp, *Hsp;
    unsigned *sWq, *sWk, *sWv, *sWo, *sW1r, *sW1i, *sW2r, *sW2i;
    float *KVf, *PSUM;
    cudaGetSymbolAddress((void**)&Nsp, g_Nsp);
    cudaGetSymbolAddress((void**)&Qsp, g_Qsp);
    cudaGetSymbolAddress((void**)&KPsp, g_KPsp);
    cudaGetSymbolAddress((void**)&VPsp, g_VPsp);
    cudaGetSymbolAddress((void**)&Dsp, g_Dsp);
    cudaGetSymbolAddress((void**)&Osp, g_Osp);
    cudaGetSymbolAddress((void**)&Hsp, g_Hsp);
    cudaGetSymbolAddress((void**)&KVf, g_KVf);
    cudaGetSymbolAddress((void**)&PSUM, g_PSUM);
    cudaGetSymbolAddress((void**)&sWq, g_Wq);
    cudaGetSymbolAddress((void**)&sWk, g_Wk);
    cudaGetSymbolAddress((void**)&sWv, g_Wv);
    cudaGetSymbolAddress((void**)&sWo, g_Wo);
    cudaGetSymbolAddress((void**)&sW1r, g_W1r);
    cudaGetSymbolAddress((void**)&sW1i, g_W1i);
    cudaGetSymbolAddress((void**)&sW2r, g_W2r);
    cudaGetSymbolAddress((void**)&sW2i, g_W2i);

    cudaMemcpyAsync(xr, x_real, ND * sizeof(float), cudaMemcpyDeviceToDevice, 0);
    cudaMemcpyAsync(xi, x_imag, ND * sizeof(float), cudaMemcpyDeviceToDevice, 0);

    const long long PQ = 262144, PF = 1048576;
    {
        conv_TB<<<(int)((PQ + 255) / 256), 256>>>(Wq, sWq, sWq + PQ, nullptr, nullptr, 256, 512);
        conv_TB<<<(int)((PQ + 255) / 256), 256>>>(Wk, sWk, sWk + PQ, nullptr, nullptr, 256, 512);
        conv_TB<<<(int)((PQ + 255) / 256), 256>>>(Wv, sWv, sWv + PQ, nullptr, nullptr, 256, 512);
        conv_TB<<<(int)((PQ + 255) / 256), 256>>>(Wout, sWo, sWo + PQ, nullptr, nullptr, 256, 512);
        conv_TB<<<(int)((PF + 255) / 256), 256>>>(W1r, sW1r, sW1r + PF, nullptr, nullptr, 256, 2048);
        conv_TB<<<(int)((PF + 255) / 256), 256>>>(W1i, sW1i, sW1i + PF, sW1i + 2 * PF, sW1i + 3 * PF, 256, 2048);
        conv_TB<<<(int)((PF + 255) / 256), 256>>>(W2r, sW2r, sW2r + PF, nullptr, nullptr, 1024, 512);
        conv_TB<<<(int)((PF + 255) / 256), 256>>>(W2i, sW2i, sW2i + PF, sW2i + 2 * PF, sW2i + 3 * PF, 1024, 512);
    }

    for (int d = 0; d < 2; d++) {
        const long long oq = (long long)d * 131072;
        const long long of = (long long)d * 524288;
        const float* bq_d = bq + (size_t)d * D_MODEL;
        const float* bk_d = bk + (size_t)d * D_MODEL;
        const float* bv_d = bv + (size_t)d * D_MODEL;
        const float* pk_d = pk + (size_t)d * N_TOK * K_LR;
        const float* pv_d = pv + (size_t)d * N_TOK * K_LR;
        const float* bo_d = bout + (size_t)d * D_MODEL;
        const float* b1r_d = b1r + (size_t)d * D_FF;
        const float* b1i_d = b1i + (size_t)d * D_FF;
        const float* b2r_d = b2r + (size_t)d * D_MODEL;
        const float* b2i_d = b2i + (size_t)d * D_MODEL;

        // ---- LN1 -> Nsp
        cln_kernel<<<N_TOK, 512>>>(xr, xi, Nsp);

        // ---- fused QKV: one launch, z = 3 weights x 2 parts (768 CTAs)
        {
            dim3 g(4, 32, 6);
            gemm_qkv<<<g, 256>>>(Nsp,
                                 sWq + oq, sWq + PQ + oq,
                                 sWk + oq, sWk + PQ + oq,
                                 sWv + oq, sWv + PQ + oq,
                                 Qsp, KVf, bq_d, bk_d, bv_d);
        }

        // ---- low-rank projections -> split KP / VP
        {
            dim3 g(D_MODEL / 128, K_LR / 128, 4 * NSPLIT);
            proj_splitk_tc<<<g, 256>>>(pk_d, pv_d, KVf, PSUM);
            proj_reduce_sp<<<(int)((4 * KDH + 255) / 256), 256>>>(PSUM, KPsp, VPsp);
        }

        // ---- complex dots -> Dsp. z = 8 heads x 2 parts.
        gemmSP(Qsp, Qsp + NDH, Qsp + 2 * NDH, Qsp + 3 * NDH,
               KPsp, KPsp + KDH, KPsp + 2 * KDH, KPsp + 3 * KDH,
               KPsp + 4 * KDH, KPsp + 5 * KDH,
               nullptr, Dsp, Dsp + HNKH, nullptr, nullptr,
               N_TOK, K_LR, DHEAD, 256, 256, 256,
               32, 32, NKH, 2 * HNKH, H_HEADS, 2, ATTN_SCALE, 0.f, 0, false);

        // ---- complex attn out -> Osp. z = 8 heads x 2 parts. N=64 tiles.
        gemmSP(Dsp, Dsp + HNKH, Dsp + 2 * HNKH, Dsp + 3 * HNKH,
               VPsp, VPsp + KDH, VPsp + 2 * KDH, VPsp + 3 * KDH,
               VPsp + 4 * KDH, VPsp + 5 * KDH,
               nullptr, Osp, Osp + NDH, nullptr, nullptr,
               N_TOK, DHEAD, K_LR, 128, 128, 512,
               NKH, 8192, 32, 2 * NDH, H_HEADS, 2, 1.f, 0.f, 0, true);

        // ---- output projection + residual (fp32). z=2 over r/i. N=64 tiles.
        gemmSP(Osp, Osp + NDH, nullptr, nullptr,
               sWo + oq, sWo + PQ + oq, nullptr, nullptr, nullptr, nullptr,
               xr, nullptr, nullptr, bo_d, nullptr,
               N_TOK, D_MODEL, D_MODEL, 256, 256, 512,
               2 * NDH, 0, ND, 0, 2, 1, 1.f, 1.f, 0, true);

        // ---- LN2 -> Nsp
        cln_kernel<<<N_TOK, 512>>>(xr, xi, Nsp);

        // ---- FFN1 (+relu) -> Hsp. z = 2 parts. N=64 tiles.
        gemmSP(Nsp, Nsp + NDH, Nsp + 2 * NDH, Nsp + 3 * NDH,
               sW1r + of, sW1r + PF + of, sW1i + of, sW1i + PF + of,
               sW1i + 2 * PF + of, sW1i + 3 * PF + of,
               nullptr, Hsp, Hsp + NFFH, b1r_d, b1i_d,
               N_TOK, D_FF, D_MODEL, 256, 256, 2048,
               0, 0, 0, 2 * NFFH, 1, 2, 1.f, 0.f, 1, true);

        // ---- FFN2 + residual (fp32). z = 2 parts. N=64 tiles.
        gemmSP(Hsp, Hsp + NFFH, Hsp + 2 * NFFH, Hsp + 3 * NFFH,
               sW2r + of, sW2r + PF + of, sW2i + of, sW2i + PF + of,
               sW2i + 2 * PF + of, sW2i + 3 * PF + of,
               xr, nullptr, nullptr, b2r_d, b2i_d,
               N_TOK, D_MODEL, D_FF, 1024, 1024, 512,
               0, 0, 0, ND, 1, 2, 1.f, 1.f, 0, true);
    }
}

// round 16
// speedup vs baseline: 1.0630x; 1.0630x over previous
#include <cuda_runtime.h>
#include <cstdint>

#define N_TOK 4096
#define D_MODEL 512
#define K_LR 256
#define H_HEADS 8
#define DHEAD 64
#define D_FF 2048
#define EPS_LN 1e-5f
#define ATTN_SCALE 0.125f
#define NSPLIT 32
#define KT 16

#define ND ((long long)N_TOK * D_MODEL)
#define KD ((long long)K_LR * D_MODEL)
#define NK ((long long)N_TOK * K_LR)
#define HNK ((long long)H_HEADS * NK)
#define NFF ((long long)N_TOK * D_FF)

#define NDH 1048576LL
#define KDH 65536LL
#define NKH 524288LL
#define HNKH 4194304LL
#define NFFH 4194304LL

// ---------------- scratch ----------------
__device__ unsigned g_Nsp[4 * NDH];
__device__ unsigned g_Qsp[4 * NDH];
__device__ float    g_KVf[4 * ND];
__device__ unsigned g_KPsp[6 * KDH];
__device__ unsigned g_VPsp[6 * KDH];
__device__ unsigned g_Dsp[4 * HNKH];
__device__ unsigned g_Osp[4 * NDH];
__device__ unsigned g_Hsp[4 * NFFH];
__device__ float    g_PSUM[4 * NSPLIT * KD];
__device__ unsigned g_Wq[2 * 262144];
__device__ unsigned g_Wk[2 * 262144];
__device__ unsigned g_Wv[2 * 262144];
__device__ unsigned g_Wo[2 * 262144];
__device__ unsigned g_W1r[2 * 1048576];
__device__ unsigned g_W1i[4 * 1048576];
__device__ unsigned g_W2r[2 * 1048576];
__device__ unsigned g_W2i[4 * 1048576];

// ---------------- helpers ----------------
__device__ __forceinline__ unsigned packbf(float x0, float x1) {
    unsigned r;
    asm("cvt.rn.bf16x2.f32 %0, %1, %2;" : "=r"(r) : "f"(x1), "f"(x0));
    return r;
}
__device__ __forceinline__ void split2(float x0, float x1, unsigned& hi, unsigned& lo) {
    hi = packbf(x0, x1);
    float h0 = __uint_as_float(hi << 16);
    float h1 = __uint_as_float(hi & 0xffff0000u);
    lo = packbf(x0 - h0, x1 - h1);
}
__device__ __forceinline__ void mma_bf16(float* c, const unsigned* a, const unsigned* b) {
    asm volatile(
        "mma.sync.aligned.m16n8k16.row.col.f32.bf16.bf16.f32 "
        "{%0,%1,%2,%3}, {%4,%5,%6,%7}, {%8,%9}, {%0,%1,%2,%3};\n"
        : "+f"(c[0]), "+f"(c[1]), "+f"(c[2]), "+f"(c[3])
        : "r"(a[0]), "r"(a[1]), "r"(a[2]), "r"(a[3]), "r"(b[0]), "r"(b[1]));
}
__device__ __forceinline__ void ldm4(unsigned* r, unsigned addr) {
    asm volatile(
        "ldmatrix.sync.aligned.m8n8.x4.shared.b16 {%0,%1,%2,%3}, [%4];"
        : "=r"(r[0]), "=r"(r[1]), "=r"(r[2]), "=r"(r[3])
        : "r"(addr));
}
__device__ __forceinline__ void cpasync16(unsigned dst, const void* src, int srcsize) {
    asm volatile("cp.async.cg.shared.global [%0], [%1], 16, %2;"
                 :: "r"(dst), "l"(src), "r"(srcsize) : "memory");
}
#define CP_COMMIT() asm volatile("cp.async.commit_group;" ::: "memory")
#define CP_WAIT1() asm volatile("cp.async.wait_group 1;" ::: "memory")

// ---------------- block reduction ----------------
__device__ __forceinline__ float blockSum(float v, float* red) {
#pragma unroll
    for (int o = 16; o > 0; o >>= 1) v += __shfl_xor_sync(0xffffffffu, v, o);
    int lane = threadIdx.x & 31, w = threadIdx.x >> 5;
    if (lane == 0) red[w] = v;
    __syncthreads();
    if (w == 0) {
        float x = (lane < 16) ? red[lane] : 0.f;
#pragma unroll
        for (int o = 8; o > 0; o >>= 1) x += __shfl_xor_sync(0xffffffffu, x, o);
        if (lane == 0) red[0] = x;
    }
    __syncthreads();
    float r = red[0];
    __syncthreads();
    return r;
}

// ---------------- complex layernorm -> split bf16 ----------------
__global__ void cln_kernel(const float* __restrict__ xr, const float* __restrict__ xi,
                           unsigned* __restrict__ Nsp) {
    __shared__ float red[16];
    int row = blockIdx.x;
    int t = threadIdx.x;
    long long base = (long long)row * D_MODEL;
    float vr = xr[base + t];
    float vi = xi[base + t];
    const float invD = 1.0f / D_MODEL;
    float mr = blockSum(vr, red) * invD;
    float mi = blockSum(vi, red) * invD;
    float cr = vr - mr, ci = vi - mi;
    float Crr = blockSum(cr * cr, red) * invD + EPS_LN;
    float Cii = blockSum(ci * ci, red) * invD + EPS_LN;
    float Cri = blockSum(cr * ci, red) * invD;
    float s = sqrtf(Crr * Cii - Cri * Cri);
    float tt = sqrtf(Cii + Crr + 2.0f * s);
    float inv = 1.0f / (s * tt);
    float Rrr = (Cii + s) * inv;
    float Rii = (Crr + s) * inv;
    float Rri = -Cri * inv;
    float outr = Rrr * cr + Rri * ci;
    float outi = Rii * ci + Rri * cr;
    float outr2 = __shfl_down_sync(0xffffffffu, outr, 1);
    float outi2 = __shfl_down_sync(0xffffffffu, outi, 1);
    if ((t & 1) == 0) {
        long long o = (long long)row * (D_MODEL / 2) + (t >> 1);
        unsigned h, l;
        split2(outr, outr2, h, l);
        Nsp[o] = h;
        Nsp[NDH + o] = l;
        split2(outi, outi2, h, l);
        Nsp[2 * NDH + o] = h;
        Nsp[3 * NDH + o] = l;
    }
}

// ---------------- cp.async 3-stage TB GEMM (R8 mainloop; HN = 64-col tiles) --
// ksplit>1: z = zz*ksplit + ks; CTA computes k-tiles [ks*ntot/ksplit, ...) and
// writes alpha*acc as dense fp32 partial to Pf + z*M*N (no bias/beta/relu).
template <bool HN>
__global__ void __launch_bounds__(256, 2) gemm_sp(
    const unsigned* __restrict__ A1h, const unsigned* __restrict__ A1l,
    const unsigned* __restrict__ A2h, const unsigned* __restrict__ A2l,
    const unsigned* __restrict__ B1h, const unsigned* __restrict__ B1l,
    const unsigned* __restrict__ B2h, const unsigned* __restrict__ B2l,
    const unsigned* __restrict__ B2nh, const unsigned* __restrict__ B2nl,
    float* __restrict__ Cf, unsigned* __restrict__ Ch, unsigned* __restrict__ Cl,
    const float* __restrict__ bias1, const float* __restrict__ bias2,
    int M, int N, int Kd, int ldap, int ldbp, int ldc,
    long long sAp, long long sBp, long long sC, long long sCp,
    float alpha, float beta, int nzc, int dorelu,
    float* __restrict__ Pf, int ksplit) {
    __shared__ unsigned smem[3 * 4096];

    const int z = blockIdx.z;
    int ks = 0, zz = z;
    if (ksplit > 1) { ks = z % ksplit; zz = z / ksplit; }
    const int part = (nzc == 2) ? (zz & 1) : 0;
    const int bz = (nzc == 2) ? (zz >> 1) : zz;

    const unsigned* Ac0h = A1h + bz * sAp;
    const unsigned* Ac0l = A1l + bz * sAp;
    const unsigned* Ac1h = A2h ? A2h + bz * sAp : nullptr;
    const unsigned* Ac1l = A2h ? A2l + bz * sAp : nullptr;
    const unsigned *Bc0h, *Bc0l, *Bc1h = nullptr, *Bc1l = nullptr;
    const float* biasz;
    if (part == 0) {
        Bc0h = B1h + bz * sBp;
        Bc0l = B1l + bz * sBp;
        if (A2h) {
            Bc1h = B2nh + bz * sBp;
            Bc1l = B2nl + bz * sBp;
        }
        biasz = bias1;
    } else {
        Bc0h = B2h + bz * sBp;
        Bc0l = B2l + bz * sBp;
        Bc1h = B1h + bz * sBp;
        Bc1l = B1l + bz * sBp;
        biasz = bias2;
    }
    float* Cfb = Cf ? Cf + bz * sC + (long long)part * sCp : nullptr;
    unsigned* Chb = Ch ? Ch + bz * sC + (long long)part * sCp : nullptr;
    unsigned* Clb = Ch ? Cl + bz * sC + (long long)part * sCp : nullptr;

    const int TILE_N = HN ? 64 : 128;
    const int brow = blockIdx.y * 128, bcol = blockIdx.x * TILE_N;
    const int tid = threadIdx.x;
    const int lane = tid & 31, w = tid >> 5;
    const int wr = HN ? (w >> 1) : (w >> 2);
    const int wc = HN ? (w & 1) : (w & 3);
    const int WROW = HN ? 32 : 64;
    const int MT = HN ? 2 : 4;
    const int gr = lane >> 2, gc = lane & 3;

    float acc[4][4][4];
#pragma unroll
    for (int i = 0; i < 4; i++)
#pragma unroll
        for (int j = 0; j < 4; j++)
#pragma unroll
            for (int q = 0; q < 4; q++) acc[i][j][q] = 0.f;

    const int am = tid >> 1, kh = tid & 1;
    const unsigned a_idx = am * 8 + ((kh ^ ((am >> 2) & 1)) * 4);

    const int lm_row = ((lane >> 3) & 1) * 8 + (lane & 7);
    const int lm_g = lane >> 4;
    const int a_mb = wr * WROW + lm_row;
    const unsigned a_frag = (a_mb * 8 + ((lm_g ^ ((a_mb >> 2) & 1)) * 4)) * 4;
    const int b_nb = wc * 32 + lm_row;
    const unsigned b_frag = (b_nb * 8 + ((lm_g ^ ((b_nb >> 2) & 1)) * 4)) * 4;

    const unsigned sbase = (unsigned)__cvta_generic_to_shared(&smem[0]);

    const int ntile1 = Kd / KT;
    const int ntot = (A2h ? 2 : 1) * ntile1;
    const int nloc = ntot / ksplit;
    const int tbase = ks * nloc;
    const int gn = bcol + am;
    const int bok = (gn < N && am < TILE_N) ? 16 : 0;
    const int gnc = bok ? gn : 0;

    auto ldst = [&](int t, int stage) {
        int ch = (t >= ntile1);
        const unsigned* Ah = ch ? Ac1h : Ac0h;
        const unsigned* Al = ch ? Ac1l : Ac0l;
        const unsigned* Bh = ch ? Bc1h : Bc0h;
        const unsigned* Bl = ch ? Bc1l : Bc0l;
        int k0p = (ch ? t - ntile1 : t) * 8;
        unsigned sa = sbase + stage * 16384 + a_idx * 4;
        long long aoff = (long long)(brow + am) * ldap + k0p + kh * 4;
        cpasync16(sa, Ah + aoff, 16);
        cpasync16(sa + 4096, Al + aoff, 16);
        long long boff = (long long)gnc * ldbp + k0p + kh * 4;
        cpasync16(sa + 8192, Bh + boff, bok);
        cpasync16(sa + 12288, Bl + boff, bok);
    };
    auto compute = [&](int stage) {
        unsigned bufA = sbase + stage * 16384;
        unsigned bufB = bufA + 8192;
        unsigned bh[4][2], bl[4][2];
#pragma unroll
        for (int p = 0; p < 2; p++) {
            unsigned r[4];
            ldm4(r, bufB + b_frag + p * 512);
            bh[2 * p][0] = r[0]; bh[2 * p + 1][0] = r[1];
            bh[2 * p][1] = r[2]; bh[2 * p + 1][1] = r[3];
            ldm4(r, bufB + 4096 + b_frag + p * 512);
            bl[2 * p][0] = r[0]; bl[2 * p + 1][0] = r[1];
            bl[2 * p][1] = r[2]; bl[2 * p + 1][1] = r[3];
        }
#pragma unroll
        for (int mt = 0; mt < MT; mt++) {
            unsigned ah[4], al[4];
            ldm4(ah, bufA + a_frag + mt * 512);
            ldm4(al, bufA + 4096 + a_frag + mt * 512);
#pragma unroll
            for (int nt = 0; nt < 4; nt++) {
                mma_bf16(acc[mt][nt], ah, bh[nt]);
                mma_bf16(acc[mt][nt], al, bh[nt]);
                mma_bf16(acc[mt][nt], ah, bl[nt]);
            }
        }
    };

    ldst(tbase, 0);
    CP_COMMIT();
    if (nloc > 1) ldst(tbase + 1, 1);
    CP_COMMIT();
    for (int tt = 0; tt < nloc; tt++) {
        CP_WAIT1();
        __syncthreads();
        if (tt + 2 < nloc) ldst(tbase + tt + 2, (tt + 2) % 3);
        CP_COMMIT();
        compute(tt % 3);
    }

    if (Pf) {
        float* Pb = Pf + (long long)z * ((long long)M * N);
#pragma unroll
        for (int mt = 0; mt < MT; mt++) {
            int m0 = brow + wr * WROW + mt * 16 + gr;
#pragma unroll
            for (int nt = 0; nt < 4; nt++) {
                int n0 = bcol + wc * 32 + nt * 8 + gc * 2;
                if (n0 >= N) continue;
                const float* c = acc[mt][nt];
                long long off = (long long)m0 * N + n0;
                *(float2*)&Pb[off] = make_float2(alpha * c[0], alpha * c[1]);
                *(float2*)&Pb[off + 8 * N] = make_float2(alpha * c[2], alpha * c[3]);
            }
        }
        return;
    }

    const int ldcP = ldc >> 1;
#pragma unroll
    for (int mt = 0; mt < MT; mt++) {
        int m0 = brow + wr * WROW + mt * 16 + gr;
#pragma unroll
        for (int nt = 0; nt < 4; nt++) {
            int n0 = bcol + wc * 32 + nt * 8 + gc * 2;
            if (n0 >= N) continue;
            const float* c = acc[mt][nt];
            float b0 = 0.f, b1v = 0.f;
            if (biasz) {
                b0 = biasz[n0];
                b1v = biasz[n0 + 1];
            }
            float v0 = alpha * c[0] + b0, v1 = alpha * c[1] + b1v;
            float v2 = alpha * c[2] + b0, v3 = alpha * c[3] + b1v;
            if (dorelu) {
                v0 = fmaxf(v0, 0.f); v1 = fmaxf(v1, 0.f);
                v2 = fmaxf(v2, 0.f); v3 = fmaxf(v3, 0.f);
            }
            if (Cfb) {
                long long off = (long long)m0 * ldc + n0;
                float2 o;
                if (beta != 0.f) {
                    o = *(const float2*)&Cfb[off];
                    v0 += beta * o.x; v1 += beta * o.y;
                }
                *(float2*)&Cfb[off] = make_float2(v0, v1);
                off += (long long)8 * ldc;
                if (beta != 0.f) {
                    o = *(const float2*)&Cfb[off];
                    v2 += beta * o.x; v3 += beta * o.y;
                }
                *(float2*)&Cfb[off] = make_float2(v2, v3);
            }
            if (Chb) {
                unsigned h, l;
                long long off = (long long)m0 * ldcP + (n0 >> 1);
                split2(v0, v1, h, l);
                Chb[off] = h; Clb[off] = l;
                off += (long long)8 * ldcP;
                split2(v2, v3, h, l);
                Chb[off] = h; Clb[off] = l;
            }
        }
    }
}

// ---- combine split-K partials: dest[p*ND + r] += P[2p][r] + P[2p+1][r] + bias_p
__global__ void combine_ks(const float* __restrict__ P, float* __restrict__ dest,
                           const float* __restrict__ bias0, const float* __restrict__ bias1) {
    long long i = (long long)blockIdx.x * blockDim.x + threadIdx.x;
    if (i >= 2 * ND) return;
    int p = (int)(i / ND);
    long long r = i % ND;
    int n = (int)(r % D_MODEL);
    float b = p ? bias1[n] : bias0[n];
    dest[i] += P[(long long)(2 * p) * ND + r] + P[(long long)(2 * p + 1) * ND + r] + b;
}

// ---------------- fused QKV GEMM: z = wsel(3) x part(2) ----------------------
__global__ void __launch_bounds__(256, 2) gemm_qkv(
    const unsigned* __restrict__ Nsp,
    const unsigned* __restrict__ Bqh, const unsigned* __restrict__ Bql,
    const unsigned* __restrict__ Bkh, const unsigned* __restrict__ Bkl,
    const unsigned* __restrict__ Bvh, const unsigned* __restrict__ Bvl,
    unsigned* __restrict__ Qsp, float* __restrict__ KVf,
    const float* __restrict__ bq, const float* __restrict__ bk,
    const float* __restrict__ bv) {
    __shared__ unsigned smem[3 * 4096];

    const int z = blockIdx.z;
    const int part = z & 1, wsel = z >> 1;
    const unsigned* Azh = Nsp + (long long)part * 2 * NDH;
    const unsigned* Azl = Azh + NDH;
    const unsigned* Bzh = (wsel == 0) ? Bqh : (wsel == 1) ? Bkh : Bvh;
    const unsigned* Bzl = (wsel == 0) ? Bql : (wsel == 1) ? Bkl : Bvl;
    const float* biasz = (wsel == 0) ? bq : (wsel == 1) ? bk : bv;
    unsigned* Chb = (wsel == 0) ? Qsp + (long long)part * 2 * NDH : nullptr;
    unsigned* Clb = Chb ? Chb + NDH : nullptr;
    float* Cfb = (wsel == 0) ? nullptr : KVf + (long long)(wsel - 1) * 2 * ND + (long long)part * ND;

    const int brow = blockIdx.y * 128, bcol = blockIdx.x * 128;
    const int tid = threadIdx.x;
    const int lane = tid & 31, w = tid >> 5;
    const int wr = w >> 2, wc = w & 3;
    const int gr = lane >> 2, gc = lane & 3;

    float acc[4][4][4];
#pragma unroll
    for (int i = 0; i < 4; i++)
#pragma unroll
        for (int j = 0; j < 4; j++)
#pragma unroll
            for (int q = 0; q < 4; q++) acc[i][j][q] = 0.f;

    const int am = tid >> 1, kh = tid & 1;
    const unsigned a_idx = am * 8 + ((kh ^ ((am >> 2) & 1)) * 4);
    const int lm_row = ((lane >> 3) & 1) * 8 + (lane & 7);
    const int lm_g = lane >> 4;
    const int a_mb = wr * 64 + lm_row;
    const unsigned a_frag = (a_mb * 8 + ((lm_g ^ ((a_mb >> 2) & 1)) * 4)) * 4;
    const int b_nb = wc * 32 + lm_row;
    const unsigned b_frag = (b_nb * 8 + ((lm_g ^ ((b_nb >> 2) & 1)) * 4)) * 4;
    const unsigned sbase = (unsigned)__cvta_generic_to_shared(&smem[0]);

    const int ntot = D_MODEL / KT;  // 32
    const int gn = bcol + am;

    auto ldst = [&](int t, int stage) {
        int k0p = t * 8;
        unsigned sa = sbase + stage * 16384 + a_idx * 4;
        long long aoff = (long long)(brow + am) * 256 + k0p + kh * 4;
        cpasync16(sa, Azh + aoff, 16);
        cpasync16(sa + 4096, Azl + aoff, 16);
        long long boff = (long long)gn * 256 + k0p + kh * 4;
        cpasync16(sa + 8192, Bzh + boff, 16);
        cpasync16(sa + 12288, Bzl + boff, 16);
    };
    auto compute = [&](int stage) {
        unsigned bufA = sbase + stage * 16384;
        unsigned bufB = bufA + 8192;
        unsigned bh[4][2], bl[4][2];
#pragma unroll
        for (int p = 0; p < 2; p++) {
            unsigned r[4];
            ldm4(r, bufB + b_frag + p * 512);
            bh[2 * p][0] = r[0]; bh[2 * p + 1][0] = r[1];
            bh[2 * p][1] = r[2]; bh[2 * p + 1][1] = r[3];
            ldm4(r, bufB + 4096 + b_frag + p * 512);
            bl[2 * p][0] = r[0]; bl[2 * p + 1][0] = r[1];
            bl[2 * p][1] = r[2]; bl[2 * p + 1][1] = r[3];
        }
#pragma unroll
        for (int mt = 0; mt < 4; mt++) {
            unsigned ah[4], al[4];
            ldm4(ah, bufA + a_frag + mt * 512);
            ldm4(al, bufA + 4096 + a_frag + mt * 512);
#pragma unroll
            for (int nt = 0; nt < 4; nt++) {
                mma_bf16(acc[mt][nt], ah, bh[nt]);
                mma_bf16(acc[mt][nt], al, bh[nt]);
                mma_bf16(acc[mt][nt], ah, bl[nt]);
            }
        }
    };

    ldst(0, 0);
    CP_COMMIT();
    ldst(1, 1);
    CP_COMMIT();
    for (int t = 0; t < ntot; t++) {
        CP_WAIT1();
        __syncthreads();
        if (t + 2 < ntot) ldst(t + 2, (t + 2) % 3);
        CP_COMMIT();
        compute(t % 3);
    }

#pragma unroll
    for (int mt = 0; mt < 4; mt++) {
        int m0 = brow + wr * 64 + mt * 16 + gr;
#pragma unroll
        for (int nt = 0; nt < 4; nt++) {
            int n0 = bcol + wc * 32 + nt * 8 + gc * 2;
            const float* c = acc[mt][nt];
            float b0 = biasz[n0], b1v = biasz[n0 + 1];
            float v0 = c[0] + b0, v1 = c[1] + b1v;
            float v2 = c[2] + b0, v3 = c[3] + b1v;
            if (Cfb) {
                long long off = (long long)m0 * 512 + n0;
                *(float2*)&Cfb[off] = make_float2(v0, v1);
                *(float2*)&Cfb[off + 8 * 512] = make_float2(v2, v3);
            } else {
                unsigned h, l;
                long long off = (long long)m0 * 256 + (n0 >> 1);
                split2(v0, v1, h, l);
                Chb[off] = h; Clb[off] = l;
                off += 8 * 256;
                split2(v2, v3, h, l);
                Chb[off] = h; Clb[off] = l;
            }
        }
    }
}

// ---------------- split-K projection (unchanged) ----------
__global__ void __launch_bounds__(256, 2) proj_splitk_tc(
    const float* __restrict__ pk, const float* __restrict__ pv,
    const float* __restrict__ KV, float* __restrict__ P) {
    __shared__ unsigned As[2][2][8 * 136];
    __shared__ unsigned Bs[2][2][8 * 136];
    const int z = blockIdx.z;
    const int p = z >> 5;
    const int s = z & 31;
    const float* A = (p < 2) ? pk : pv;
    const float* B = KV + (long long)p * ND;
    const int chunk = N_TOK / NSPLIT;
    const int kbeg = s * chunk;
    const int brow = blockIdx.y * 128, bcol = blockIdx.x * 128;
    const int tid = threadIdx.x;
    const int lane = tid & 31, w = tid >> 5;
    const int wr = w >> 2, wc = w & 3;
    const int gr = lane >> 2, gc = lane & 3;
    const int kp = tid >> 5;
    const int an = lane * 4;

    float acc[4][4][4];
#pragma unroll
    for (int i = 0; i < 4; i++)
#pragma unroll
        for (int j = 0; j < 4; j++)
#pragma unroll
            for (int q = 0; q < 4; q++) acc[i][j][q] = 0.f;

    float4 pa0, pa1, pb0, pb1;
    auto ld = [&](int k0) {
        pa0 = *(const float4*)&A[(long long)(k0 + 2 * kp) * K_LR + brow + an];
        pa1 = *(const float4*)&A[(long long)(k0 + 2 * kp + 1) * K_LR + brow + an];
        pb0 = *(const float4*)&B[(long long)(k0 + 2 * kp) * D_MODEL + bcol + an];
        pb1 = *(const float4*)&B[(long long)(k0 + 2 * kp + 1) * D_MODEL + bcol + an];
    };
    auto st = [&](int buf) {
        unsigned h, l;
        unsigned base = kp * 136 + an;
        split2(pa0.x, pa1.x, h, l); As[buf][0][base + 0] = h; As[buf][1][base + 0] = l;
        split2(pa0.y, pa1.y, h, l); As[buf][0][base + 1] = h; As[buf][1][base + 1] = l;
        split2(pa0.z, pa1.z, h, l); As[buf][0][base + 2] = h; As[buf][1][base + 2] = l;
        split2(pa0.w, pa1.w, h, l); As[buf][0][base + 3] = h; As[buf][1][base + 3] = l;
        split2(pb0.x, pb1.x, h, l); Bs[buf][0][base + 0] = h; Bs[buf][1][base + 0] = l;
        split2(pb0.y, pb1.y, h, l); Bs[buf][0][base + 1] = h; Bs[buf][1][base + 1] = l;
        split2(pb0.z, pb1.z, h, l); Bs[buf][0][base + 2] = h; Bs[buf][1][base + 2] = l;
        split2(pb0.w, pb1.w, h, l); Bs[buf][0][base + 3] = h; Bs[buf][1][base + 3] = l;
    };
    auto compute = [&](int buf) {
        unsigned bh[4][2], bl[4][2];
#pragma unroll
        for (int nt = 0; nt < 4; nt++) {
            int n = wc * 32 + nt * 8 + gr;
            bh[nt][0] = Bs[buf][0][gc * 136 + n];
            bh[nt][1] = Bs[buf][0][(gc + 4) * 136 + n];
            bl[nt][0] = Bs[buf][1][gc * 136 + n];
            bl[nt][1] = Bs[buf][1][(gc + 4) * 136 + n];
        }
#pragma unroll
        for (int mt = 0; mt < 4; mt++) {
            int m = wr * 64 + mt * 16;
            unsigned ah[4], al[4];
            ah[0] = As[buf][0][gc * 136 + m + gr];
            ah[1] = As[buf][0][gc * 136 + m + 8 + gr];
            ah[2] = As[buf][0][(gc + 4) * 136 + m + gr];
            ah[3] = As[buf][0][(gc + 4) * 136 + m + 8 + gr];
            al[0] = As[buf][1][gc * 136 + m + gr];
            al[1] = As[buf][1][gc * 136 + m + 8 + gr];
            al[2] = As[buf][1][(gc + 4) * 136 + m + gr];
            al[3] = As[buf][1][(gc + 4) * 136 + m + 8 + gr];
#pragma unroll
            for (int nt = 0; nt < 4; nt++) {
                mma_bf16(acc[mt][nt], ah, bh[nt]);
                mma_bf16(acc[mt][nt], al, bh[nt]);
                mma_bf16(acc[mt][nt], ah, bl[nt]);
            }
        }
    };

    ld(kbeg);
    st(0);
    __syncthreads();
    const int ntile = chunk / KT;
    for (int t = 0; t < ntile; t++) {
        if (t + 1 < ntile) ld(kbeg + (t + 1) * KT);
        compute(t & 1);
        if (t + 1 < ntile) st((t + 1) & 1);
        __syncthreads();
    }

    float* Pz = P + (long long)z * KD;
#pragma unroll
    for (int mt = 0; mt < 4; mt++) {
        int m0 = brow + wr * 64 + mt * 16 + gr;
#pragma unroll
        for (int nt = 0; nt < 4; nt++) {
            int n0 = bcol + wc * 32 + nt * 8 + gc * 2;
            const float* c = acc[mt][nt];
            *(float2*)&Pz[(long long)m0 * D_MODEL + n0] = make_float2(c[0], c[1]);
            *(float2*)&Pz[(long long)(m0 + 8) * D_MODEL + n0] = make_float2(c[2], c[3]);
        }
    }
}

// reduce split-K partials; KP: [K_LR][D/2] pairs along D; VP: TB [D][K_LR/2]
__global__ void proj_reduce_sp(const float* __restrict__ P,
                               unsigned* __restrict__ KP, unsigned* __restrict__ VP) {
    const int half = (int)KDH;
    int i = blockIdx.x * blockDim.x + threadIdx.x;
    if (i >= 4 * half) return;
    int p = i / half, j = i % half;
    long long e0, e1;
    if (p < 2) {
        int row = j / (D_MODEL / 2), c = j % (D_MODEL / 2);
        e0 = (long long)row * D_MODEL + 2 * c;
        e1 = e0 + 1;
    } else {
        int dm = j / (K_LR / 2), kp2 = j % (K_LR / 2);
        e0 = (long long)(2 * kp2) * D_MODEL + dm;
        e1 = e0 + D_MODEL;
    }
    const float* base = P + (long long)p * NSPLIT * KD;
    float s0 = 0.f, s1 = 0.f;
#pragma unroll 8
    for (int s = 0; s < NSPLIT; s++) {
        s0 += base[(long long)s * KD + e0];
        s1 += base[(long long)s * KD + e1];
    }
    unsigned h, l;
    split2(s0, s1, h, l);
    unsigned* T = (p < 2) ? KP : VP;
    int q = p & 1;
    T[(long long)(2 * q) * half + j] = h;
    T[(long long)(2 * q + 1) * half + j] = l;
    if (q == 1) {
        T[4LL * half + j] = h ^ 0x80008000u;
        T[5LL * half + j] = l ^ 0x80008000u;
    }
}

// fp32 W [DEPTH][Kd][N] -> TB split [depth][N][Kd/2] (+ optional negated)
__global__ void conv_TB(const float* __restrict__ W, unsigned* __restrict__ Wh,
                        unsigned* __restrict__ Wl, unsigned* __restrict__ Wnh,
                        unsigned* __restrict__ Wnl, int halfK, int N) {
    long long i = (long long)blockIdx.x * blockDim.x + threadIdx.x;
    long long per = (long long)halfK * N;
    if (i >= 2 * per) return;
    int d = (int)(i / per);
    long long r = i % per;
    int n = (int)(r / halfK);
    int kp = (int)(r % halfK);
    long long src = ((long long)d * 2 * halfK + 2 * kp) * N + n;
    unsigned h, l;
    split2(W[src], W[src + N], h, l);
    long long o = (long long)d * per + (long long)n * halfK + kp;
    Wh[o] = h;
    Wl[o] = l;
    if (Wnh) {
        Wnh[o] = h ^ 0x80008000u;
        Wnl[o] = l ^ 0x80008000u;
    }
}

// ---------------- host launcher ----------------
static inline void gemmSP(const unsigned* A1h, const unsigned* A1l,
                          const unsigned* A2h, const unsigned* A2l,
                          const unsigned* B1h, const unsigned* B1l,
                          const unsigned* B2h, const unsigned* B2l,
                          const unsigned* B2nh, const unsigned* B2nl,
                          float* Cf, unsigned* Ch, unsigned* Cl,
                          const float* b1, const float* b2,
                          int M, int N, int Kd, int ldap, int ldbp, int ldc,
                          long long sAp, long long sBp, long long sC, long long sCp,
                          int nbatch, int nzc, float alpha, float beta, int relu,
                          bool hn, float* Pf = nullptr, int ksplit = 1) {
    if (hn) {
        dim3 grid((N + 63) / 64, (M + 127) / 128, nbatch * nzc * ksplit);
        gemm_sp<true><<<grid, 256>>>(A1h, A1l, A2h, A2l, B1h, B1l, B2h, B2l, B2nh, B2nl,
                                     Cf, Ch, Cl, b1, b2, M, N, Kd, ldap, ldbp, ldc,
                                     sAp, sBp, sC, sCp, alpha, beta, nzc, relu, Pf, ksplit);
    } else {
        dim3 grid((N + 127) / 128, (M + 127) / 128, nbatch * nzc * ksplit);
        gemm_sp<false><<<grid, 256>>>(A1h, A1l, A2h, A2l, B1h, B1l, B2h, B2l, B2nh, B2nl,
                                      Cf, Ch, Cl, b1, b2, M, N, Kd, ldap, ldbp, ldc,
                                      sAp, sBp, sC, sCp, alpha, beta, nzc, relu, Pf, ksplit);
    }
}

extern "C" void kernel_launch(void* const* d_in, const int* in_sizes, int n_in,
                              void* d_out, int out_size) {
    const float* x_real = (const float*)d_in[0];
    const float* x_imag = (const float*)d_in[1];
    const float* Wq = (const float*)d_in[2];
    const float* bq = (const float*)d_in[3];
    const float* Wk = (const float*)d_in[4];
    const float* bk = (const float*)d_in[5];
    const float* Wv = (const float*)d_in[6];
    const float* bv = (const float*)d_in[7];
    const float* pk = (const float*)d_in[8];
    const float* pv = (const float*)d_in[9];
    const float* Wout = (const float*)d_in[10];
    const float* bout = (const float*)d_in[11];
    const float* W1r = (const float*)d_in[12];
    const float* W1i = (const float*)d_in[13];
    const float* b1r = (const float*)d_in[14];
    const float* b1i = (const float*)d_in[15];
    const float* W2r = (const float*)d_in[16];
    const float* W2i = (const float*)d_in[17];
    const float* b2r = (const float*)d_in[18];
    const float* b2i = (const float*)d_in[19];

    float* xr = (float*)d_out;
    float* xi = xr + ND;

    unsigned *Nsp, *Qsp, *KPsp, *VPsp, *Dsp, *Osp, *Hsp;
    unsigned *sWq, *sWk, *sWv, *sWo, *sW1r, *sW1i, *sW2r, *sW2i;
    float *KVf, *PSUM;
    cudaGetSymbolAddress((void**)&Nsp, g_Nsp);
    cudaGetSymbolAddress((void**)&Qsp, g_Qsp);
    cudaGetSymbolAddress((void**)&KPsp, g_KPsp);
    cudaGetSymbolAddress((void**)&VPsp, g_VPsp);
    cudaGetSymbolAddress((void**)&Dsp, g_Dsp);
    cudaGetSymbolAddress((void**)&Osp, g_Osp);
    cudaGetSymbolAddress((void**)&Hsp, g_Hsp);
    cudaGetSymbolAddress((void**)&KVf, g_KVf);
    cudaGetSymbolAddress((void**)&PSUM, g_PSUM);
    cudaGetSymbolAddress((void**)&sWq, g_Wq);
    cudaGetSymbolAddress((void**)&sWk, g_Wk);
    cudaGetSymbolAddress((void**)&sWv, g_Wv);
    cudaGetSymbolAddress((void**)&sWo, g_Wo);
    cudaGetSymbolAddress((void**)&sW1r, g_W1r);
    cudaGetSymbolAddress((void**)&sW1i, g_W1i);
    cudaGetSymbolAddress((void**)&sW2r, g_W2r);
    cudaGetSymbolAddress((void**)&sW2i, g_W2i);

    cudaMemcpyAsync(xr, x_real, ND * sizeof(float), cudaMemcpyDeviceToDevice, 0);
    cudaMemcpyAsync(xi, x_imag, ND * sizeof(float), cudaMemcpyDeviceToDevice, 0);

    const long long PQ = 262144, PF = 1048576;
    {
        conv_TB<<<(int)((PQ + 255) / 256), 256>>>(Wq, sWq, sWq + PQ, nullptr, nullptr, 256, 512);
        conv_TB<<<(int)((PQ + 255) / 256), 256>>>(Wk, sWk, sWk + PQ, nullptr, nullptr, 256, 512);
        conv_TB<<<(int)((PQ + 255) / 256), 256>>>(Wv, sWv, sWv + PQ, nullptr, nullptr, 256, 512);
        conv_TB<<<(int)((PQ + 255) / 256), 256>>>(Wout, sWo, sWo + PQ, nullptr, nullptr, 256, 512);
        conv_TB<<<(int)((PF + 255) / 256), 256>>>(W1r, sW1r, sW1r + PF, nullptr, nullptr, 256, 2048);
        conv_TB<<<(int)((PF + 255) / 256), 256>>>(W1i, sW1i, sW1i + PF, sW1i + 2 * PF, sW1i + 3 * PF, 256, 2048);
        conv_TB<<<(int)((PF + 255) / 256), 256>>>(W2r, sW2r, sW2r + PF, nullptr, nullptr, 1024, 512);
        conv_TB<<<(int)((PF + 255) / 256), 256>>>(W2i, sW2i, sW2i + PF, sW2i + 2 * PF, sW2i + 3 * PF, 1024, 512);
    }

    for (int d = 0; d < 2; d++) {
        const long long oq = (long long)d * 131072;
        const long long of = (long long)d * 524288;
        const float* bq_d = bq + (size_t)d * D_MODEL;
        const float* bk_d = bk + (size_t)d * D_MODEL;
        const float* bv_d = bv + (size_t)d * D_MODEL;
        const float* pk_d = pk + (size_t)d * N_TOK * K_LR;
        const float* pv_d = pv + (size_t)d * N_TOK * K_LR;
        const float* bo_d = bout + (size_t)d * D_MODEL;
        const float* b1r_d = b1r + (size_t)d * D_FF;
        const float* b1i_d = b1i + (size_t)d * D_FF;
        const float* b2r_d = b2r + (size_t)d * D_MODEL;
        const float* b2i_d = b2i + (size_t)d * D_MODEL;

        // ---- LN1 -> Nsp
        cln_kernel<<<N_TOK, 512>>>(xr, xi, Nsp);

        // ---- fused QKV: one launch, z = 3 weights x 2 parts (768 CTAs)
        {
            dim3 g(4, 32, 6);
            gemm_qkv<<<g, 256>>>(Nsp,
                                 sWq + oq, sWq + PQ + oq,
                                 sWk + oq, sWk + PQ + oq,
                                 sWv + oq, sWv + PQ + oq,
                                 Qsp, KVf, bq_d, bk_d, bv_d);
        }

        // ---- low-rank projections -> split KP / VP
        {
            dim3 g(D_MODEL / 128, K_LR / 128, 4 * NSPLIT);
            proj_splitk_tc<<<g, 256>>>(pk_d, pv_d, KVf, PSUM);
            proj_reduce_sp<<<(int)((4 * KDH + 255) / 256), 256>>>(PSUM, KPsp, VPsp);
        }

        // ---- complex dots -> Dsp. z = 8 heads x 2 parts.
        gemmSP(Qsp, Qsp + NDH, Qsp + 2 * NDH, Qsp + 3 * NDH,
               KPsp, KPsp + KDH, KPsp + 2 * KDH, KPsp + 3 * KDH,
               KPsp + 4 * KDH, KPsp + 5 * KDH,
               nullptr, Dsp, Dsp + HNKH, nullptr, nullptr,
               N_TOK, K_LR, DHEAD, 256, 256, 256,
               32, 32, NKH, 2 * HNKH, H_HEADS, 2, ATTN_SCALE, 0.f, 0, false);

        // ---- complex attn out -> Osp. z = 8 heads x 2 parts. N=64 tiles.
        gemmSP(Dsp, Dsp + HNKH, Dsp + 2 * HNKH, Dsp + 3 * HNKH,
               VPsp, VPsp + KDH, VPsp + 2 * KDH, VPsp + 3 * KDH,
               VPsp + 4 * KDH, VPsp + 5 * KDH,
               nullptr, Osp, Osp + NDH, nullptr, nullptr,
               N_TOK, DHEAD, K_LR, 128, 128, 512,
               NKH, 8192, 32, 2 * NDH, H_HEADS, 2, 1.f, 0.f, 0, true);

        // ---- output projection: split-K x2 partials -> combine(+bias+residual)
        gemmSP(Osp, Osp + NDH, nullptr, nullptr,
               sWo + oq, sWo + PQ + oq, nullptr, nullptr, nullptr, nullptr,
               nullptr, nullptr, nullptr, nullptr, nullptr,
               N_TOK, D_MODEL, D_MODEL, 256, 256, 512,
               2 * NDH, 0, 0, 0, 2, 1, 1.f, 0.f, 0, false, PSUM, 2);
        combine_ks<<<(int)((2 * ND + 255) / 256), 256>>>(PSUM, xr, bo_d, bo_d);

        // ---- LN2 -> Nsp
        cln_kernel<<<N_TOK, 512>>>(xr, xi, Nsp);

        // ---- FFN1 (+relu) -> Hsp. z = 2 parts.
        gemmSP(Nsp, Nsp + NDH, Nsp + 2 * NDH, Nsp + 3 * NDH,
               sW1r + of, sW1r + PF + of, sW1i + of, sW1i + PF + of,
               sW1i + 2 * PF + of, sW1i + 3 * PF + of,
               nullptr, Hsp, Hsp + NFFH, b1r_d, b1i_d,
               N_TOK, D_FF, D_MODEL, 256, 256, 2048,
               0, 0, 0, 2 * NFFH, 1, 2, 1.f, 0.f, 1, false);

        // ---- FFN2: split-K x2 partials -> combine(+bias+residual)
        gemmSP(Hsp, Hsp + NFFH, Hsp + 2 * NFFH, Hsp + 3 * NFFH,
               sW2r + of, sW2r + PF + of, sW2i + of, sW2i + PF + of,
               sW2i + 2 * PF + of, sW2i + 3 * PF + of,
               nullptr, nullptr, nullptr, nullptr, nullptr,
               N_TOK, D_MODEL, D_FF, 1024, 1024, 512,
               0, 0, 0, 0, 1, 2, 1.f, 0.f, 0, false, PSUM, 2);
        combine_ks<<<(int)((2 * ND + 255) / 256), 256>>>(PSUM, xr, b2r_d, b2i_d);
    }
}

// round 17
// speedup vs baseline: 1.0813x; 1.0172x over previous
#include <cuda_runtime.h>
#include <cstdint>

#define N_TOK 4096
#define D_MODEL 512
#define K_LR 256
#define H_HEADS 8
#define DHEAD 64
#define D_FF 2048
#define EPS_LN 1e-5f
#define ATTN_SCALE 0.125f
#define NSPLIT 32
#define KT 16

#define ND ((long long)N_TOK * D_MODEL)
#define KD ((long long)K_LR * D_MODEL)
#define NK ((long long)N_TOK * K_LR)
#define HNK ((long long)H_HEADS * NK)
#define NFF ((long long)N_TOK * D_FF)

#define NDH 1048576LL
#define KDH 65536LL
#define NKH 524288LL
#define HNKH 4194304LL
#define NFFH 4194304LL

// ---------------- scratch ----------------
__device__ unsigned g_Nsp[4 * NDH];
__device__ unsigned g_Qsp[4 * NDH];
__device__ float    g_KVf[4 * ND];
__device__ unsigned g_KPsp[6 * KDH];
__device__ unsigned g_VPsp[6 * KDH];
__device__ unsigned g_Dsp[4 * HNKH];
__device__ unsigned g_Osp[4 * NDH];
__device__ unsigned g_Hsp[4 * NFFH];
__device__ float    g_PSUM[4 * NSPLIT * KD];
__device__ unsigned g_Wq[2 * 262144];
__device__ unsigned g_Wk[2 * 262144];
__device__ unsigned g_Wv[2 * 262144];
__device__ unsigned g_Wo[2 * 262144];
__device__ unsigned g_W1r[2 * 1048576];
__device__ unsigned g_W1i[4 * 1048576];
__device__ unsigned g_W2r[2 * 1048576];
__device__ unsigned g_W2i[4 * 1048576];

// ---------------- helpers ----------------
__device__ __forceinline__ unsigned packbf(float x0, float x1) {
    unsigned r;
    asm("cvt.rn.bf16x2.f32 %0, %1, %2;" : "=r"(r) : "f"(x1), "f"(x0));
    return r;
}
__device__ __forceinline__ void split2(float x0, float x1, unsigned& hi, unsigned& lo) {
    hi = packbf(x0, x1);
    float h0 = __uint_as_float(hi << 16);
    float h1 = __uint_as_float(hi & 0xffff0000u);
    lo = packbf(x0 - h0, x1 - h1);
}
__device__ __forceinline__ void mma_bf16(float* c, const unsigned* a, const unsigned* b) {
    asm volatile(
        "mma.sync.aligned.m16n8k16.row.col.f32.bf16.bf16.f32 "
        "{%0,%1,%2,%3}, {%4,%5,%6,%7}, {%8,%9}, {%0,%1,%2,%3};\n"
        : "+f"(c[0]), "+f"(c[1]), "+f"(c[2]), "+f"(c[3])
        : "r"(a[0]), "r"(a[1]), "r"(a[2]), "r"(a[3]), "r"(b[0]), "r"(b[1]));
}
__device__ __forceinline__ void ldm4(unsigned* r, unsigned addr) {
    asm volatile(
        "ldmatrix.sync.aligned.m8n8.x4.shared.b16 {%0,%1,%2,%3}, [%4];"
        : "=r"(r[0]), "=r"(r[1]), "=r"(r[2]), "=r"(r[3])
        : "r"(addr));
}
__device__ __forceinline__ void cpasync16(unsigned dst, const void* src, int srcsize) {
    asm volatile("cp.async.cg.shared.global [%0], [%1], 16, %2;"
                 :: "r"(dst), "l"(src), "r"(srcsize) : "memory");
}
#define CP_COMMIT() asm volatile("cp.async.commit_group;" ::: "memory")
#define CP_WAIT1() asm volatile("cp.async.wait_group 1;" ::: "memory")

// ---------------- multi-value block reductions (bit-identical trees) ---------
__device__ __forceinline__ void blockSum2(float& a, float& b, float* red) {
#pragma unroll
    for (int o = 16; o > 0; o >>= 1) {
        a += __shfl_xor_sync(0xffffffffu, a, o);
        b += __shfl_xor_sync(0xffffffffu, b, o);
    }
    int lane = threadIdx.x & 31, w = threadIdx.x >> 5;
    if (lane == 0) { red[w] = a; red[16 + w] = b; }
    __syncthreads();
    if (w == 0) {
        float x = (lane < 16) ? red[lane] : 0.f;
        float y = (lane < 16) ? red[16 + lane] : 0.f;
#pragma unroll
        for (int o = 8; o > 0; o >>= 1) {
            x += __shfl_xor_sync(0xffffffffu, x, o);
            y += __shfl_xor_sync(0xffffffffu, y, o);
        }
        if (lane == 0) { red[0] = x; red[16] = y; }
    }
    __syncthreads();
    a = red[0];
    b = red[16];
    __syncthreads();
}
__device__ __forceinline__ void blockSum3(float& a, float& b, float& c, float* red) {
#pragma unroll
    for (int o = 16; o > 0; o >>= 1) {
        a += __shfl_xor_sync(0xffffffffu, a, o);
        b += __shfl_xor_sync(0xffffffffu, b, o);
        c += __shfl_xor_sync(0xffffffffu, c, o);
    }
    int lane = threadIdx.x & 31, w = threadIdx.x >> 5;
    if (lane == 0) { red[w] = a; red[16 + w] = b; red[32 + w] = c; }
    __syncthreads();
    if (w == 0) {
        float x = (lane < 16) ? red[lane] : 0.f;
        float y = (lane < 16) ? red[16 + lane] : 0.f;
        float zv = (lane < 16) ? red[32 + lane] : 0.f;
#pragma unroll
        for (int o = 8; o > 0; o >>= 1) {
            x += __shfl_xor_sync(0xffffffffu, x, o);
            y += __shfl_xor_sync(0xffffffffu, y, o);
            zv += __shfl_xor_sync(0xffffffffu, zv, o);
        }
        if (lane == 0) { red[0] = x; red[16] = y; red[32] = zv; }
    }
    __syncthreads();
    a = red[0];
    b = red[16];
    c = red[32];
    __syncthreads();
}

// ---------------- complex layernorm (optional fused split-K combine) ---------
// If P != null: xr/xi get updated in place with xr += (P0+P1)+bias0,
// xi += (P2+P3)+bias1 (same association as combine_ks), then LN runs on the
// updated values and emits split bf16 Nsp.
__global__ void cln_kernel(float* __restrict__ xr, float* __restrict__ xi,
                           const float* __restrict__ P,
                           const float* __restrict__ bias0,
                           const float* __restrict__ bias1,
                           unsigned* __restrict__ Nsp) {
    __shared__ float red[48];
    int row = blockIdx.x;
    int t = threadIdx.x;
    long long base = (long long)row * D_MODEL;
    float vr = xr[base + t];
    float vi = xi[base + t];
    if (P) {
        float ar = (P[base + t] + P[ND + base + t]) + bias0[t];
        vr = vr + ar;
        xr[base + t] = vr;
        float ai = (P[2 * ND + base + t] + P[3 * ND + base + t]) + bias1[t];
        vi = vi + ai;
        xi[base + t] = vi;
    }
    const float invD = 1.0f / D_MODEL;
    float mr = vr, mi = vi;
    blockSum2(mr, mi, red);
    mr *= invD;
    mi *= invD;
    float cr = vr - mr, ci = vi - mi;
    float Crr = cr * cr, Cii = ci * ci, Cri = cr * ci;
    blockSum3(Crr, Cii, Cri, red);
    Crr = Crr * invD + EPS_LN;
    Cii = Cii * invD + EPS_LN;
    Cri = Cri * invD;
    float s = sqrtf(Crr * Cii - Cri * Cri);
    float tt = sqrtf(Cii + Crr + 2.0f * s);
    float inv = 1.0f / (s * tt);
    float Rrr = (Cii + s) * inv;
    float Rii = (Crr + s) * inv;
    float Rri = -Cri * inv;
    float outr = Rrr * cr + Rri * ci;
    float outi = Rii * ci + Rri * cr;
    float outr2 = __shfl_down_sync(0xffffffffu, outr, 1);
    float outi2 = __shfl_down_sync(0xffffffffu, outi, 1);
    if ((t & 1) == 0) {
        long long o = (long long)row * (D_MODEL / 2) + (t >> 1);
        unsigned h, l;
        split2(outr, outr2, h, l);
        Nsp[o] = h;
        Nsp[NDH + o] = l;
        split2(outi, outi2, h, l);
        Nsp[2 * NDH + o] = h;
        Nsp[3 * NDH + o] = l;
    }
}

// ---------------- cp.async 3-stage TB GEMM (R8 mainloop; HN = 64-col tiles) --
template <bool HN>
__global__ void __launch_bounds__(256, 2) gemm_sp(
    const unsigned* __restrict__ A1h, const unsigned* __restrict__ A1l,
    const unsigned* __restrict__ A2h, const unsigned* __restrict__ A2l,
    const unsigned* __restrict__ B1h, const unsigned* __restrict__ B1l,
    const unsigned* __restrict__ B2h, const unsigned* __restrict__ B2l,
    const unsigned* __restrict__ B2nh, const unsigned* __restrict__ B2nl,
    float* __restrict__ Cf, unsigned* __restrict__ Ch, unsigned* __restrict__ Cl,
    const float* __restrict__ bias1, const float* __restrict__ bias2,
    int M, int N, int Kd, int ldap, int ldbp, int ldc,
    long long sAp, long long sBp, long long sC, long long sCp,
    float alpha, float beta, int nzc, int dorelu,
    float* __restrict__ Pf, int ksplit) {
    __shared__ unsigned smem[3 * 4096];

    const int z = blockIdx.z;
    int ks = 0, zz = z;
    if (ksplit > 1) { ks = z % ksplit; zz = z / ksplit; }
    const int part = (nzc == 2) ? (zz & 1) : 0;
    const int bz = (nzc == 2) ? (zz >> 1) : zz;

    const unsigned* Ac0h = A1h + bz * sAp;
    const unsigned* Ac0l = A1l + bz * sAp;
    const unsigned* Ac1h = A2h ? A2h + bz * sAp : nullptr;
    const unsigned* Ac1l = A2h ? A2l + bz * sAp : nullptr;
    const unsigned *Bc0h, *Bc0l, *Bc1h = nullptr, *Bc1l = nullptr;
    const float* biasz;
    if (part == 0) {
        Bc0h = B1h + bz * sBp;
        Bc0l = B1l + bz * sBp;
        if (A2h) {
            Bc1h = B2nh + bz * sBp;
            Bc1l = B2nl + bz * sBp;
        }
        biasz = bias1;
    } else {
        Bc0h = B2h + bz * sBp;
        Bc0l = B2l + bz * sBp;
        Bc1h = B1h + bz * sBp;
        Bc1l = B1l + bz * sBp;
        biasz = bias2;
    }
    float* Cfb = Cf ? Cf + bz * sC + (long long)part * sCp : nullptr;
    unsigned* Chb = Ch ? Ch + bz * sC + (long long)part * sCp : nullptr;
    unsigned* Clb = Ch ? Cl + bz * sC + (long long)part * sCp : nullptr;

    const int TILE_N = HN ? 64 : 128;
    const int brow = blockIdx.y * 128, bcol = blockIdx.x * TILE_N;
    const int tid = threadIdx.x;
    const int lane = tid & 31, w = tid >> 5;
    const int wr = HN ? (w >> 1) : (w >> 2);
    const int wc = HN ? (w & 1) : (w & 3);
    const int WROW = HN ? 32 : 64;
    const int MT = HN ? 2 : 4;
    const int gr = lane >> 2, gc = lane & 3;

    float acc[4][4][4];
#pragma unroll
    for (int i = 0; i < 4; i++)
#pragma unroll
        for (int j = 0; j < 4; j++)
#pragma unroll
            for (int q = 0; q < 4; q++) acc[i][j][q] = 0.f;

    const int am = tid >> 1, kh = tid & 1;
    const unsigned a_idx = am * 8 + ((kh ^ ((am >> 2) & 1)) * 4);

    const int lm_row = ((lane >> 3) & 1) * 8 + (lane & 7);
    const int lm_g = lane >> 4;
    const int a_mb = wr * WROW + lm_row;
    const unsigned a_frag = (a_mb * 8 + ((lm_g ^ ((a_mb >> 2) & 1)) * 4)) * 4;
    const int b_nb = wc * 32 + lm_row;
    const unsigned b_frag = (b_nb * 8 + ((lm_g ^ ((b_nb >> 2) & 1)) * 4)) * 4;

    const unsigned sbase = (unsigned)__cvta_generic_to_shared(&smem[0]);

    const int ntile1 = Kd / KT;
    const int ntot = (A2h ? 2 : 1) * ntile1;
    const int nloc = ntot / ksplit;
    const int tbase = ks * nloc;
    const int gn = bcol + am;
    const int bok = (gn < N && am < TILE_N) ? 16 : 0;
    const int gnc = bok ? gn : 0;

    auto ldst = [&](int t, int stage) {
        int ch = (t >= ntile1);
        const unsigned* Ah = ch ? Ac1h : Ac0h;
        const unsigned* Al = ch ? Ac1l : Ac0l;
        const unsigned* Bh = ch ? Bc1h : Bc0h;
        const unsigned* Bl = ch ? Bc1l : Bc0l;
        int k0p = (ch ? t - ntile1 : t) * 8;
        unsigned sa = sbase + stage * 16384 + a_idx * 4;
        long long aoff = (long long)(brow + am) * ldap + k0p + kh * 4;
        cpasync16(sa, Ah + aoff, 16);
        cpasync16(sa + 4096, Al + aoff, 16);
        long long boff = (long long)gnc * ldbp + k0p + kh * 4;
        cpasync16(sa + 8192, Bh + boff, bok);
        cpasync16(sa + 12288, Bl + boff, bok);
    };
    auto compute = [&](int stage) {
        unsigned bufA = sbase + stage * 16384;
        unsigned bufB = bufA + 8192;
        unsigned bh[4][2], bl[4][2];
#pragma unroll
        for (int p = 0; p < 2; p++) {
            unsigned r[4];
            ldm4(r, bufB + b_frag + p * 512);
            bh[2 * p][0] = r[0]; bh[2 * p + 1][0] = r[1];
            bh[2 * p][1] = r[2]; bh[2 * p + 1][1] = r[3];
            ldm4(r, bufB + 4096 + b_frag + p * 512);
            bl[2 * p][0] = r[0]; bl[2 * p + 1][0] = r[1];
            bl[2 * p][1] = r[2]; bl[2 * p + 1][1] = r[3];
        }
#pragma unroll
        for (int mt = 0; mt < MT; mt++) {
            unsigned ah[4], al[4];
            ldm4(ah, bufA + a_frag + mt * 512);
            ldm4(al, bufA + 4096 + a_frag + mt * 512);
#pragma unroll
            for (int nt = 0; nt < 4; nt++) {
                mma_bf16(acc[mt][nt], ah, bh[nt]);
                mma_bf16(acc[mt][nt], al, bh[nt]);
                mma_bf16(acc[mt][nt], ah, bl[nt]);
            }
        }
    };

    ldst(tbase, 0);
    CP_COMMIT();
    if (nloc > 1) ldst(tbase + 1, 1);
    CP_COMMIT();
    for (int tt = 0; tt < nloc; tt++) {
        CP_WAIT1();
        __syncthreads();
        if (tt + 2 < nloc) ldst(tbase + tt + 2, (tt + 2) % 3);
        CP_COMMIT();
        compute(tt % 3);
    }

    if (Pf) {
        float* Pb = Pf + (long long)z * ((long long)M * N);
#pragma unroll
        for (int mt = 0; mt < MT; mt++) {
            int m0 = brow + wr * WROW + mt * 16 + gr;
#pragma unroll
            for (int nt = 0; nt < 4; nt++) {
                int n0 = bcol + wc * 32 + nt * 8 + gc * 2;
                if (n0 >= N) continue;
                const float* c = acc[mt][nt];
                long long off = (long long)m0 * N + n0;
                *(float2*)&Pb[off] = make_float2(alpha * c[0], alpha * c[1]);
                *(float2*)&Pb[off + 8 * N] = make_float2(alpha * c[2], alpha * c[3]);
            }
        }
        return;
    }

    const int ldcP = ldc >> 1;
#pragma unroll
    for (int mt = 0; mt < MT; mt++) {
        int m0 = brow + wr * WROW + mt * 16 + gr;
#pragma unroll
        for (int nt = 0; nt < 4; nt++) {
            int n0 = bcol + wc * 32 + nt * 8 + gc * 2;
            if (n0 >= N) continue;
            const float* c = acc[mt][nt];
            float b0 = 0.f, b1v = 0.f;
            if (biasz) {
                b0 = biasz[n0];
                b1v = biasz[n0 + 1];
            }
            float v0 = alpha * c[0] + b0, v1 = alpha * c[1] + b1v;
            float v2 = alpha * c[2] + b0, v3 = alpha * c[3] + b1v;
            if (dorelu) {
                v0 = fmaxf(v0, 0.f); v1 = fmaxf(v1, 0.f);
                v2 = fmaxf(v2, 0.f); v3 = fmaxf(v3, 0.f);
            }
            if (Cfb) {
                long long off = (long long)m0 * ldc + n0;
                float2 o;
                if (beta != 0.f) {
                    o = *(const float2*)&Cfb[off];
                    v0 += beta * o.x; v1 += beta * o.y;
                }
                *(float2*)&Cfb[off] = make_float2(v0, v1);
                off += (long long)8 * ldc;
                if (beta != 0.f) {
                    o = *(const float2*)&Cfb[off];
                    v2 += beta * o.x; v3 += beta * o.y;
                }
                *(float2*)&Cfb[off] = make_float2(v2, v3);
            }
            if (Chb) {
                unsigned h, l;
                long long off = (long long)m0 * ldcP + (n0 >> 1);
                split2(v0, v1, h, l);
                Chb[off] = h; Clb[off] = l;
                off += (long long)8 * ldcP;
                split2(v2, v3, h, l);
                Chb[off] = h; Clb[off] = l;
            }
        }
    }
}

// ---- combine split-K partials (standalone; used only after final FFN2) ----
__global__ void combine_ks(const float* __restrict__ P, float* __restrict__ dest,
                           const float* __restrict__ bias0, const float* __restrict__ bias1) {
    long long i = (long long)blockIdx.x * blockDim.x + threadIdx.x;
    if (i >= 2 * ND) return;
    int p = (int)(i / ND);
    long long r = i % ND;
    int n = (int)(r % D_MODEL);
    float b = p ? bias1[n] : bias0[n];
    dest[i] += P[(long long)(2 * p) * ND + r] + P[(long long)(2 * p + 1) * ND + r] + b;
}

// ---------------- fused QKV GEMM: z = wsel(3) x part(2) ----------------------
__global__ void __launch_bounds__(256, 2) gemm_qkv(
    const unsigned* __restrict__ Nsp,
    const unsigned* __restrict__ Bqh, const unsigned* __restrict__ Bql,
    const unsigned* __restrict__ Bkh, const unsigned* __restrict__ Bkl,
    const unsigned* __restrict__ Bvh, const unsigned* __restrict__ Bvl,
    unsigned* __restrict__ Qsp, float* __restrict__ KVf,
    const float* __restrict__ bq, const float* __restrict__ bk,
    const float* __restrict__ bv) {
    __shared__ unsigned smem[3 * 4096];

    const int z = blockIdx.z;
    const int part = z & 1, wsel = z >> 1;
    const unsigned* Azh = Nsp + (long long)part * 2 * NDH;
    const unsigned* Azl = Azh + NDH;
    const unsigned* Bzh = (wsel == 0) ? Bqh : (wsel == 1) ? Bkh : Bvh;
    const unsigned* Bzl = (wsel == 0) ? Bql : (wsel == 1) ? Bkl : Bvl;
    const float* biasz = (wsel == 0) ? bq : (wsel == 1) ? bk : bv;
    unsigned* Chb = (wsel == 0) ? Qsp + (long long)part * 2 * NDH : nullptr;
    unsigned* Clb = Chb ? Chb + NDH : nullptr;
    float* Cfb = (wsel == 0) ? nullptr : KVf + (long long)(wsel - 1) * 2 * ND + (long long)part * ND;

    const int brow = blockIdx.y * 128, bcol = blockIdx.x * 128;
    const int tid = threadIdx.x;
    const int lane = tid & 31, w = tid >> 5;
    const int wr = w >> 2, wc = w & 3;
    const int gr = lane >> 2, gc = lane & 3;

    float acc[4][4][4];
#pragma unroll
    for (int i = 0; i < 4; i++)
#pragma unroll
        for (int j = 0; j < 4; j++)
#pragma unroll
            for (int q = 0; q < 4; q++) acc[i][j][q] = 0.f;

    const int am = tid >> 1, kh = tid & 1;
    const unsigned a_idx = am * 8 + ((kh ^ ((am >> 2) & 1)) * 4);
    const int lm_row = ((lane >> 3) & 1) * 8 + (lane & 7);
    const int lm_g = lane >> 4;
    const int a_mb = wr * 64 + lm_row;
    const unsigned a_frag = (a_mb * 8 + ((lm_g ^ ((a_mb >> 2) & 1)) * 4)) * 4;
    const int b_nb = wc * 32 + lm_row;
    const unsigned b_frag = (b_nb * 8 + ((lm_g ^ ((b_nb >> 2) & 1)) * 4)) * 4;
    const unsigned sbase = (unsigned)__cvta_generic_to_shared(&smem[0]);

    const int ntot = D_MODEL / KT;  // 32
    const int gn = bcol + am;

    auto ldst = [&](int t, int stage) {
        int k0p = t * 8;
        unsigned sa = sbase + stage * 16384 + a_idx * 4;
        long long aoff = (long long)(brow + am) * 256 + k0p + kh * 4;
        cpasync16(sa, Azh + aoff, 16);
        cpasync16(sa + 4096, Azl + aoff, 16);
        long long boff = (long long)gn * 256 + k0p + kh * 4;
        cpasync16(sa + 8192, Bzh + boff, 16);
        cpasync16(sa + 12288, Bzl + boff, 16);
    };
    auto compute = [&](int stage) {
        unsigned bufA = sbase + stage * 16384;
        unsigned bufB = bufA + 8192;
        unsigned bh[4][2], bl[4][2];
#pragma unroll
        for (int p = 0; p < 2; p++) {
            unsigned r[4];
            ldm4(r, bufB + b_frag + p * 512);
            bh[2 * p][0] = r[0]; bh[2 * p + 1][0] = r[1];
            bh[2 * p][1] = r[2]; bh[2 * p + 1][1] = r[3];
            ldm4(r, bufB + 4096 + b_frag + p * 512);
            bl[2 * p][0] = r[0]; bl[2 * p + 1][0] = r[1];
            bl[2 * p][1] = r[2]; bl[2 * p + 1][1] = r[3];
        }
#pragma unroll
        for (int mt = 0; mt < 4; mt++) {
            unsigned ah[4], al[4];
            ldm4(ah, bufA + a_frag + mt * 512);
            ldm4(al, bufA + 4096 + a_frag + mt * 512);
#pragma unroll
            for (int nt = 0; nt < 4; nt++) {
                mma_bf16(acc[mt][nt], ah, bh[nt]);
                mma_bf16(acc[mt][nt], al, bh[nt]);
                mma_bf16(acc[mt][nt], ah, bl[nt]);
            }
        }
    };

    ldst(0, 0);
    CP_COMMIT();
    ldst(1, 1);
    CP_COMMIT();
    for (int t = 0; t < ntot; t++) {
        CP_WAIT1();
        __syncthreads();
        if (t + 2 < ntot) ldst(t + 2, (t + 2) % 3);
        CP_COMMIT();
        compute(t % 3);
    }

#pragma unroll
    for (int mt = 0; mt < 4; mt++) {
        int m0 = brow + wr * 64 + mt * 16 + gr;
#pragma unroll
        for (int nt = 0; nt < 4; nt++) {
            int n0 = bcol + wc * 32 + nt * 8 + gc * 2;
            const float* c = acc[mt][nt];
            float b0 = biasz[n0], b1v = biasz[n0 + 1];
            float v0 = c[0] + b0, v1 = c[1] + b1v;
            float v2 = c[2] + b0, v3 = c[3] + b1v;
            if (Cfb) {
                long long off = (long long)m0 * 512 + n0;
                *(float2*)&Cfb[off] = make_float2(v0, v1);
                *(float2*)&Cfb[off + 8 * 512] = make_float2(v2, v3);
            } else {
                unsigned h, l;
                long long off = (long long)m0 * 256 + (n0 >> 1);
                split2(v0, v1, h, l);
                Chb[off] = h; Clb[off] = l;
                off += 8 * 256;
                split2(v2, v3, h, l);
                Chb[off] = h; Clb[off] = l;
            }
        }
    }
}

// ---------------- split-K projection (unchanged) ----------
__global__ void __launch_bounds__(256, 2) proj_splitk_tc(
    const float* __restrict__ pk, const float* __restrict__ pv,
    const float* __restrict__ KV, float* __restrict__ P) {
    __shared__ unsigned As[2][2][8 * 136];
    __shared__ unsigned Bs[2][2][8 * 136];
    const int z = blockIdx.z;
    const int p = z >> 5;
    const int s = z & 31;
    const float* A = (p < 2) ? pk : pv;
    const float* B = KV + (long long)p * ND;
    const int chunk = N_TOK / NSPLIT;
    const int kbeg = s * chunk;
    const int brow = blockIdx.y * 128, bcol = blockIdx.x * 128;
    const int tid = threadIdx.x;
    const int lane = tid & 31, w = tid >> 5;
    const int wr = w >> 2, wc = w & 3;
    const int gr = lane >> 2, gc = lane & 3;
    const int kp = tid >> 5;
    const int an = lane * 4;

    float acc[4][4][4];
#pragma unroll
    for (int i = 0; i < 4; i++)
#pragma unroll
        for (int j = 0; j < 4; j++)
#pragma unroll
            for (int q = 0; q < 4; q++) acc[i][j][q] = 0.f;

    float4 pa0, pa1, pb0, pb1;
    auto ld = [&](int k0) {
        pa0 = *(const float4*)&A[(long long)(k0 + 2 * kp) * K_LR + brow + an];
        pa1 = *(const float4*)&A[(long long)(k0 + 2 * kp + 1) * K_LR + brow + an];
        pb0 = *(const float4*)&B[(long long)(k0 + 2 * kp) * D_MODEL + bcol + an];
        pb1 = *(const float4*)&B[(long long)(k0 + 2 * kp + 1) * D_MODEL + bcol + an];
    };
    auto st = [&](int buf) {
        unsigned h, l;
        unsigned base = kp * 136 + an;
        split2(pa0.x, pa1.x, h, l); As[buf][0][base + 0] = h; As[buf][1][base + 0] = l;
        split2(pa0.y, pa1.y, h, l); As[buf][0][base + 1] = h; As[buf][1][base + 1] = l;
        split2(pa0.z, pa1.z, h, l); As[buf][0][base + 2] = h; As[buf][1][base + 2] = l;
        split2(pa0.w, pa1.w, h, l); As[buf][0][base + 3] = h; As[buf][1][base + 3] = l;
        split2(pb0.x, pb1.x, h, l); Bs[buf][0][base + 0] = h; Bs[buf][1][base + 0] = l;
        split2(pb0.y, pb1.y, h, l); Bs[buf][0][base + 1] = h; Bs[buf][1][base + 1] = l;
        split2(pb0.z, pb1.z, h, l); Bs[buf][0][base + 2] = h; Bs[buf][1][base + 2] = l;
        split2(pb0.w, pb1.w, h, l); Bs[buf][0][base + 3] = h; Bs[buf][1][base + 3] = l;
    };
    auto compute = [&](int buf) {
        unsigned bh[4][2], bl[4][2];
#pragma unroll
        for (int nt = 0; nt < 4; nt++) {
            int n = wc * 32 + nt * 8 + gr;
            bh[nt][0] = Bs[buf][0][gc * 136 + n];
            bh[nt][1] = Bs[buf][0][(gc + 4) * 136 + n];
            bl[nt][0] = Bs[buf][1][gc * 136 + n];
            bl[nt][1] = Bs[buf][1][(gc + 4) * 136 + n];
        }
#pragma unroll
        for (int mt = 0; mt < 4; mt++) {
            int m = wr * 64 + mt * 16;
            unsigned ah[4], al[4];
            ah[0] = As[buf][0][gc * 136 + m + gr];
            ah[1] = As[buf][0][gc * 136 + m + 8 + gr];
            ah[2] = As[buf][0][(gc + 4) * 136 + m + gr];
            ah[3] = As[buf][0][(gc + 4) * 136 + m + 8 + gr];
            al[0] = As[buf][1][gc * 136 + m + gr];
            al[1] = As[buf][1][gc * 136 + m + 8 + gr];
            al[2] = As[buf][1][(gc + 4) * 136 + m + gr];
            al[3] = As[buf][1][(gc + 4) * 136 + m + 8 + gr];
#pragma unroll
            for (int nt = 0; nt < 4; nt++) {
                mma_bf16(acc[mt][nt], ah, bh[nt]);
                mma_bf16(acc[mt][nt], al, bh[nt]);
                mma_bf16(acc[mt][nt], ah, bl[nt]);
            }
        }
    };

    ld(kbeg);
    st(0);
    __syncthreads();
    const int ntile = chunk / KT;
    for (int t = 0; t < ntile; t++) {
        if (t + 1 < ntile) ld(kbeg + (t + 1) * KT);
        compute(t & 1);
        if (t + 1 < ntile) st((t + 1) & 1);
        __syncthreads();
    }

    float* Pz = P + (long long)z * KD;
#pragma unroll
    for (int mt = 0; mt < 4; mt++) {
        int m0 = brow + wr * 64 + mt * 16 + gr;
#pragma unroll
        for (int nt = 0; nt < 4; nt++) {
            int n0 = bcol + wc * 32 + nt * 8 + gc * 2;
            const float* c = acc[mt][nt];
            *(float2*)&Pz[(long long)m0 * D_MODEL + n0] = make_float2(c[0], c[1]);
            *(float2*)&Pz[(long long)(m0 + 8) * D_MODEL + n0] = make_float2(c[2], c[3]);
        }
    }
}

// reduce split-K partials; KP: [K_LR][D/2] pairs along D; VP: TB [D][K_LR/2]
__global__ void proj_reduce_sp(const float* __restrict__ P,
                               unsigned* __restrict__ KP, unsigned* __restrict__ VP) {
    const int half = (int)KDH;
    int i = blockIdx.x * blockDim.x + threadIdx.x;
    if (i >= 4 * half) return;
    int p = i / half, j = i % half;
    long long e0, e1;
    if (p < 2) {
        int row = j / (D_MODEL / 2), c = j % (D_MODEL / 2);
        e0 = (long long)row * D_MODEL + 2 * c;
        e1 = e0 + 1;
    } else {
        int dm = j / (K_LR / 2), kp2 = j % (K_LR / 2);
        e0 = (long long)(2 * kp2) * D_MODEL + dm;
        e1 = e0 + D_MODEL;
    }
    const float* base = P + (long long)p * NSPLIT * KD;
    float s0 = 0.f, s1 = 0.f;
#pragma unroll 8
    for (int s = 0; s < NSPLIT; s++) {
        s0 += base[(long long)s * KD + e0];
        s1 += base[(long long)s * KD + e1];
    }
    unsigned h, l;
    split2(s0, s1, h, l);
    unsigned* T = (p < 2) ? KP : VP;
    int q = p & 1;
    T[(long long)(2 * q) * half + j] = h;
    T[(long long)(2 * q + 1) * half + j] = l;
    if (q == 1) {
        T[4LL * half + j] = h ^ 0x80008000u;
        T[5LL * half + j] = l ^ 0x80008000u;
    }
}

// fp32 W [DEPTH][Kd][N] -> TB split [depth][N][Kd/2] (+ optional negated)
__global__ void conv_TB(const float* __restrict__ W, unsigned* __restrict__ Wh,
                        unsigned* __restrict__ Wl, unsigned* __restrict__ Wnh,
                        unsigned* __restrict__ Wnl, int halfK, int N) {
    long long i = (long long)blockIdx.x * blockDim.x + threadIdx.x;
    long long per = (long long)halfK * N;
    if (i >= 2 * per) return;
    int d = (int)(i / per);
    long long r = i % per;
    int n = (int)(r / halfK);
    int kp = (int)(r % halfK);
    long long src = ((long long)d * 2 * halfK + 2 * kp) * N + n;
    unsigned h, l;
    split2(W[src], W[src + N], h, l);
    long long o = (long long)d * per + (long long)n * halfK + kp;
    Wh[o] = h;
    Wl[o] = l;
    if (Wnh) {
        Wnh[o] = h ^ 0x80008000u;
        Wnl[o] = l ^ 0x80008000u;
    }
}

// ---------------- host launcher ----------------
static inline void gemmSP(const unsigned* A1h, const unsigned* A1l,
                          const unsigned* A2h, const unsigned* A2l,
                          const unsigned* B1h, const unsigned* B1l,
                          const unsigned* B2h, const unsigned* B2l,
                          const unsigned* B2nh, const unsigned* B2nl,
                          float* Cf, unsigned* Ch, unsigned* Cl,
                          const float* b1, const float* b2,
                          int M, int N, int Kd, int ldap, int ldbp, int ldc,
                          long long sAp, long long sBp, long long sC, long long sCp,
                          int nbatch, int nzc, float alpha, float beta, int relu,
                          bool hn, float* Pf = nullptr, int ksplit = 1) {
    if (hn) {
        dim3 grid((N + 63) / 64, (M + 127) / 128, nbatch * nzc * ksplit);
        gemm_sp<true><<<grid, 256>>>(A1h, A1l, A2h, A2l, B1h, B1l, B2h, B2l, B2nh, B2nl,
                                     Cf, Ch, Cl, b1, b2, M, N, Kd, ldap, ldbp, ldc,
                                     sAp, sBp, sC, sCp, alpha, beta, nzc, relu, Pf, ksplit);
    } else {
        dim3 grid((N + 127) / 128, (M + 127) / 128, nbatch * nzc * ksplit);
        gemm_sp<false><<<grid, 256>>>(A1h, A1l, A2h, A2l, B1h, B1l, B2h, B2l, B2nh, B2nl,
                                      Cf, Ch, Cl, b1, b2, M, N, Kd, ldap, ldbp, ldc,
                                      sAp, sBp, sC, sCp, alpha, beta, nzc, relu, Pf, ksplit);
    }
}

extern "C" void kernel_launch(void* const* d_in, const int* in_sizes, int n_in,
                              void* d_out, int out_size) {
    const float* x_real = (const float*)d_in[0];
    const float* x_imag = (const float*)d_in[1];
    const float* Wq = (const float*)d_in[2];
    const float* bq = (const float*)d_in[3];
    const float* Wk = (const float*)d_in[4];
    const float* bk = (const float*)d_in[5];
    const float* Wv = (const float*)d_in[6];
    const float* bv = (const float*)d_in[7];
    const float* pk = (const float*)d_in[8];
    const float* pv = (const float*)d_in[9];
    const float* Wout = (const float*)d_in[10];
    const float* bout = (const float*)d_in[11];
    const float* W1r = (const float*)d_in[12];
    const float* W1i = (const float*)d_in[13];
    const float* b1r = (const float*)d_in[14];
    const float* b1i = (const float*)d_in[15];
    const float* W2r = (const float*)d_in[16];
    const float* W2i = (const float*)d_in[17];
    const float* b2r = (const float*)d_in[18];
    const float* b2i = (const float*)d_in[19];

    float* xr = (float*)d_out;
    float* xi = xr + ND;

    unsigned *Nsp, *Qsp, *KPsp, *VPsp, *Dsp, *Osp, *Hsp;
    unsigned *sWq, *sWk, *sWv, *sWo, *sW1r, *sW1i, *sW2r, *sW2i;
    float *KVf, *PSUM;
    cudaGetSymbolAddress((void**)&Nsp, g_Nsp);
    cudaGetSymbolAddress((void**)&Qsp, g_Qsp);
    cudaGetSymbolAddress((void**)&KPsp, g_KPsp);
    cudaGetSymbolAddress((void**)&VPsp, g_VPsp);
    cudaGetSymbolAddress((void**)&Dsp, g_Dsp);
    cudaGetSymbolAddress((void**)&Osp, g_Osp);
    cudaGetSymbolAddress((void**)&Hsp, g_Hsp);
    cudaGetSymbolAddress((void**)&KVf, g_KVf);
    cudaGetSymbolAddress((void**)&PSUM, g_PSUM);
    cudaGetSymbolAddress((void**)&sWq, g_Wq);
    cudaGetSymbolAddress((void**)&sWk, g_Wk);
    cudaGetSymbolAddress((void**)&sWv, g_Wv);
    cudaGetSymbolAddress((void**)&sWo, g_Wo);
    cudaGetSymbolAddress((void**)&sW1r, g_W1r);
    cudaGetSymbolAddress((void**)&sW1i, g_W1i);
    cudaGetSymbolAddress((void**)&sW2r, g_W2r);
    cudaGetSymbolAddress((void**)&sW2i, g_W2i);

    cudaMemcpyAsync(xr, x_real, ND * sizeof(float), cudaMemcpyDeviceToDevice, 0);
    cudaMemcpyAsync(xi, x_imag, ND * sizeof(float), cudaMemcpyDeviceToDevice, 0);

    const long long PQ = 262144, PF = 1048576;
    {
        conv_TB<<<(int)((PQ + 255) / 256), 256>>>(Wq, sWq, sWq + PQ, nullptr, nullptr, 256, 512);
        conv_TB<<<(int)((PQ + 255) / 256), 256>>>(Wk, sWk, sWk + PQ, nullptr, nullptr, 256, 512);
        conv_TB<<<(int)((PQ + 255) / 256), 256>>>(Wv, sWv, sWv + PQ, nullptr, nullptr, 256, 512);
        conv_TB<<<(int)((PQ + 255) / 256), 256>>>(Wout, sWo, sWo + PQ, nullptr, nullptr, 256, 512);
        conv_TB<<<(int)((PF + 255) / 256), 256>>>(W1r, sW1r, sW1r + PF, nullptr, nullptr, 256, 2048);
        conv_TB<<<(int)((PF + 255) / 256), 256>>>(W1i, sW1i, sW1i + PF, sW1i + 2 * PF, sW1i + 3 * PF, 256, 2048);
        conv_TB<<<(int)((PF + 255) / 256), 256>>>(W2r, sW2r, sW2r + PF, nullptr, nullptr, 1024, 512);
        conv_TB<<<(int)((PF + 255) / 256), 256>>>(W2i, sW2i, sW2i + PF, sW2i + 2 * PF, sW2i + 3 * PF, 1024, 512);
    }

    for (int d = 0; d < 2; d++) {
        const long long oq = (long long)d * 131072;
        const long long of = (long long)d * 524288;
        const float* bq_d = bq + (size_t)d * D_MODEL;
        const float* bk_d = bk + (size_t)d * D_MODEL;
        const float* bv_d = bv + (size_t)d * D_MODEL;
        const float* pk_d = pk + (size_t)d * N_TOK * K_LR;
        const float* pv_d = pv + (size_t)d * N_TOK * K_LR;
        const float* bo_d = bout + (size_t)d * D_MODEL;
        const float* b1r_d = b1r + (size_t)d * D_FF;
        const float* b1i_d = b1i + (size_t)d * D_FF;
        const float* b2r_d = b2r + (size_t)d * D_MODEL;
        const float* b2i_d = b2i + (size_t)d * D_MODEL;

        // ---- LN1 -> Nsp. Depth 1 fuses the pending FFN2 combine of depth 0.
        if (d == 0)
            cln_kernel<<<N_TOK, 512>>>(xr, xi, nullptr, nullptr, nullptr, Nsp);
        else
            cln_kernel<<<N_TOK, 512>>>(xr, xi, PSUM, b2r, b2i, Nsp);

        // ---- fused QKV: one launch, z = 3 weights x 2 parts (768 CTAs)
        {
            dim3 g(4, 32, 6);
            gemm_qkv<<<g, 256>>>(Nsp,
                                 sWq + oq, sWq + PQ + oq,
                                 sWk + oq, sWk + PQ + oq,
                                 sWv + oq, sWv + PQ + oq,
                                 Qsp, KVf, bq_d, bk_d, bv_d);
        }

        // ---- low-rank projections -> split KP / VP
        {
            dim3 g(D_MODEL / 128, K_LR / 128, 4 * NSPLIT);
            proj_splitk_tc<<<g, 256>>>(pk_d, pv_d, KVf, PSUM);
            proj_reduce_sp<<<(int)((4 * KDH + 255) / 256), 256>>>(PSUM, KPsp, VPsp);
        }

        // ---- complex dots -> Dsp. z = 8 heads x 2 parts.
        gemmSP(Qsp, Qsp + NDH, Qsp + 2 * NDH, Qsp + 3 * NDH,
               KPsp, KPsp + KDH, KPsp + 2 * KDH, KPsp + 3 * KDH,
               KPsp + 4 * KDH, KPsp + 5 * KDH,
               nullptr, Dsp, Dsp + HNKH, nullptr, nullptr,
               N_TOK, K_LR, DHEAD, 256, 256, 256,
               32, 32, NKH, 2 * HNKH, H_HEADS, 2, ATTN_SCALE, 0.f, 0, false);

        // ---- complex attn out -> Osp. z = 8 heads x 2 parts. N=64 tiles.
        gemmSP(Dsp, Dsp + HNKH, Dsp + 2 * HNKH, Dsp + 3 * HNKH,
               VPsp, VPsp + KDH, VPsp + 2 * KDH, VPsp + 3 * KDH,
               VPsp + 4 * KDH, VPsp + 5 * KDH,
               nullptr, Osp, Osp + NDH, nullptr, nullptr,
               N_TOK, DHEAD, K_LR, 128, 128, 512,
               NKH, 8192, 32, 2 * NDH, H_HEADS, 2, 1.f, 0.f, 0, true);

        // ---- output projection: split-K x2 partials (combine fused into LN2)
        gemmSP(Osp, Osp + NDH, nullptr, nullptr,
               sWo + oq, sWo + PQ + oq, nullptr, nullptr, nullptr, nullptr,
               nullptr, nullptr, nullptr, nullptr, nullptr,
               N_TOK, D_MODEL, D_MODEL, 256, 256, 512,
               2 * NDH, 0, 0, 0, 2, 1, 1.f, 0.f, 0, false, PSUM, 2);

        // ---- LN2 (fused combine of out-proj partials) -> Nsp
        cln_kernel<<<N_TOK, 512>>>(xr, xi, PSUM, bo_d, bo_d, Nsp);

        // ---- FFN1 (+relu) -> Hsp. z = 2 parts.
        gemmSP(Nsp, Nsp + NDH, Nsp + 2 * NDH, Nsp + 3 * NDH,
               sW1r + of, sW1r + PF + of, sW1i + of, sW1i + PF + of,
               sW1i + 2 * PF + of, sW1i + 3 * PF + of,
               nullptr, Hsp, Hsp + NFFH, b1r_d, b1i_d,
               N_TOK, D_FF, D_MODEL, 256, 256, 2048,
               0, 0, 0, 2 * NFFH, 1, 2, 1.f, 0.f, 1, false);

        // ---- FFN2: split-K x2 partials. Depth 0: combine deferred into next
        //      LN1. Depth 1: standalone combine into final output.
        gemmSP(Hsp, Hsp + NFFH, Hsp + 2 * NFFH, Hsp + 3 * NFFH,
               sW2r + of, sW2r + PF + of, sW2i + of, sW2i + PF + of,
               sW2i + 2 * PF + of, sW2i + 3 * PF + of,
               nullptr, nullptr, nullptr, nullptr, nullptr,
               N_TOK, D_MODEL, D_FF, 1024, 1024, 512,
               0, 0, 0, 0, 1, 2, 1.f, 0.f, 0, false, PSUM, 2);
        if (d == 1)
            combine_ks<<<(int)((2 * ND + 255) / 256), 256>>>(PSUM, xr, b2r_d, b2i_d);
    }
}